// round 1
// baseline (speedup 1.0000x reference)
#include <cuda_runtime.h>
#include <cuda_bf16.h>
#include <math.h>

// Problem constants (dataset is fixed)
#define NN 50000
#define EE 800000

// ---------------- device scratch (no allocs allowed) ----------------
__device__ float g_bufA[NN * 256];
__device__ float g_bufB[NN * 256];
__device__ float g_z[NN * 64];
__device__ int   g_deg[NN];
__device__ float g_dinv[NN];
__device__ float g_dinv2[NN];
__device__ int   g_rowstart[NN + 1];
__device__ int   g_cursor[NN];
__device__ int   g_src32[EE];
__device__ int   g_dst32[EE];
__device__ int   g_csr_src[EE];
__device__ float g_csr_norm[EE];
__device__ float g_t1[NN];
__device__ float g_t2[NN];
__device__ int   g_flag[1];

// ---------------- edge-index dtype detect + convert ----------------
__global__ void detect_kernel(const long long* ei) {
    if (blockIdx.x == 0 && threadIdx.x == 0) {
        int ok = 1;
        for (int i = 0; i < 128; i++) {
            long long v = ei[i];
            if (v < 0 || v >= NN) { ok = 0; break; }
        }
        g_flag[0] = ok;  // 1 = int64, 0 = int32
    }
}

__global__ void convert_kernel(const void* ei, int E) {
    int i = blockIdx.x * blockDim.x + threadIdx.x;
    if (i >= E) return;
    if (g_flag[0]) {
        const long long* p = (const long long*)ei;
        g_src32[i] = (int)p[i];
        g_dst32[i] = (int)p[i + E];
    } else {
        const int* p = (const int*)ei;
        g_src32[i] = p[i];
        g_dst32[i] = p[i + E];
    }
}

// ---------------- degree / norm prep ----------------
__global__ void zero_deg_kernel(int n) {
    int i = blockIdx.x * blockDim.x + threadIdx.x;
    if (i < n) g_deg[i] = 0;
}

__global__ void hist_kernel(int E) {
    int i = blockIdx.x * blockDim.x + threadIdx.x;
    if (i >= E) return;
    atomicAdd(&g_deg[g_dst32[i]], 1);
}

__global__ void dinv_kernel(int n) {
    int v = blockIdx.x * blockDim.x + threadIdx.x;
    if (v >= n) return;
    float d = (float)(g_deg[v] + 1);
    float di = rsqrtf(d);
    g_dinv[v]  = di;
    g_dinv2[v] = di * di;
}

// single-block exclusive scan (n up to 50000)
__global__ void scan_kernel(int n) {
    __shared__ int wsum[32];
    __shared__ int s_carry;
    int tid = threadIdx.x;
    if (tid == 0) s_carry = 0;
    __syncthreads();
    int nch = (n + 1023) / 1024;
    for (int c = 0; c < nch; c++) {
        int i = c * 1024 + tid;
        int v = (i < n) ? g_deg[i] : 0;
        int x = v;
        #pragma unroll
        for (int o = 1; o < 32; o <<= 1) {
            int t = __shfl_up_sync(0xffffffffu, x, o);
            if ((tid & 31) >= o) x += t;
        }
        if ((tid & 31) == 31) wsum[tid >> 5] = x;
        __syncthreads();
        if (tid < 32) {
            int w = wsum[tid];
            #pragma unroll
            for (int o = 1; o < 32; o <<= 1) {
                int t = __shfl_up_sync(0xffffffffu, w, o);
                if (tid >= o) w += t;
            }
            wsum[tid] = w;
        }
        __syncthreads();
        int incl = x + ((tid >= 32) ? wsum[(tid >> 5) - 1] : 0) + s_carry;
        if (i < n) { g_rowstart[i] = incl - v; g_cursor[i] = incl - v; }
        __syncthreads();
        if (tid == 0) s_carry += wsum[31];
        __syncthreads();
    }
    if (tid == 0) g_rowstart[n] = s_carry;
}

__global__ void scatter_kernel(int E) {
    int i = blockIdx.x * blockDim.x + threadIdx.x;
    if (i >= E) return;
    int s = g_src32[i], d = g_dst32[i];
    int pos = atomicAdd(&g_cursor[d], 1);
    g_csr_src[pos]  = s;
    g_csr_norm[pos] = g_dinv[s] * g_dinv[d];
}

// ---------------- tiled SGEMM: C[M,Nc] = A[M,K] @ B[K,Nc] (+bias) ----------------
template<int FUSE_BIAS>
__global__ __launch_bounds__(256) void sgemm_kernel(
    const float* __restrict__ A, const float* __restrict__ B,
    const float* __restrict__ bias, float* __restrict__ C,
    int M, int Nc, int K)
{
    __shared__ float As[16][68];
    __shared__ float Bs[16][64];
    int tid = threadIdx.x;
    int tx = tid & 15, ty = tid >> 4;
    int bm = blockIdx.y * 64, bn = blockIdx.x * 64;
    float acc[4][4];
    #pragma unroll
    for (int i = 0; i < 4; i++)
        #pragma unroll
        for (int j = 0; j < 4; j++) acc[i][j] = 0.f;

    for (int k0 = 0; k0 < K; k0 += 16) {
        #pragma unroll
        for (int l = 0; l < 4; l++) {
            int idx = tid + l * 256;       // 0..1023
            int r = idx >> 4, kk = idx & 15;
            int row = bm + r;
            As[kk][r] = (row < M) ? A[(size_t)row * K + k0 + kk] : 0.f;
        }
        #pragma unroll
        for (int l = 0; l < 4; l++) {
            int idx = tid + l * 256;
            int kk = idx >> 6, c = idx & 63;
            Bs[kk][c] = B[(size_t)(k0 + kk) * Nc + bn + c];
        }
        __syncthreads();
        #pragma unroll
        for (int kk = 0; kk < 16; kk++) {
            float4 a4 = *(const float4*)&As[kk][ty * 4];
            float4 b4 = *(const float4*)&Bs[kk][tx * 4];
            float a[4] = {a4.x, a4.y, a4.z, a4.w};
            float b[4] = {b4.x, b4.y, b4.z, b4.w};
            #pragma unroll
            for (int i = 0; i < 4; i++)
                #pragma unroll
                for (int j = 0; j < 4; j++)
                    acc[i][j] += a[i] * b[j];
        }
        __syncthreads();
    }
    #pragma unroll
    for (int i = 0; i < 4; i++) {
        int row = bm + ty * 4 + i;
        if (row >= M) continue;
        #pragma unroll
        for (int j = 0; j < 4; j++) {
            int col = bn + tx * 4 + j;
            float v = acc[i][j];
            if (FUSE_BIAS) v += bias[col];
            C[(size_t)row * Nc + col] = v;
        }
    }
}

// ---------------- CSR gather aggregation (warp per node) ----------------
// out[v] = sum_{e in in(v)} h[src_e] * norm_e + h[v]*dinv2[v] + bias  (opt relu)
template<int F, int RELU>
__global__ __launch_bounds__(256) void agg_kernel(
    const float* __restrict__ h, const float* __restrict__ bias,
    float* __restrict__ out, int N)
{
    int gw = (blockIdx.x * blockDim.x + threadIdx.x) >> 5;
    int lane = threadIdx.x & 31;
    if (gw >= N) return;
    constexpr int V = F / 32;
    float acc[V];
    #pragma unroll
    for (int i = 0; i < V; i++) acc[i] = 0.f;
    int e0 = g_rowstart[gw], e1 = g_rowstart[gw + 1];
    const float* base = h + lane * V;
    #pragma unroll 2
    for (int e = e0; e < e1; e++) {
        int s = __ldg(&g_csr_src[e]);
        float w = __ldg(&g_csr_norm[e]);
        const float* r = base + (size_t)s * F;
        if (V == 2) {
            float2 x2 = *(const float2*)r;
            acc[0] += x2.x * w; acc[1] += x2.y * w;
        } else {
            #pragma unroll
            for (int i = 0; i < V; i += 4) {
                float4 x4 = *(const float4*)(r + i);
                acc[i + 0] += x4.x * w; acc[i + 1] += x4.y * w;
                acc[i + 2] += x4.z * w; acc[i + 3] += x4.w * w;
            }
        }
    }
    float sw = g_dinv2[gw];
    const float* sr = base + (size_t)gw * F;
    float* o = out + (size_t)gw * F + lane * V;
    #pragma unroll
    for (int i = 0; i < V; i++) {
        float val = acc[i] + sr[i] * sw + bias[lane * V + i];
        if (RELU) val = fmaxf(val, 0.f);
        o[i] = val;
    }
}

// ---------------- link predictor ----------------
__global__ void lp_node_kernel(const float* __restrict__ z,
                               const float* __restrict__ lw, int N)
{
    int v = blockIdx.x * blockDim.x + threadIdx.x;
    if (v >= N) return;
    const float4* zr = (const float4*)(z + (size_t)v * 64);
    float a = 0.f, b = 0.f;
    #pragma unroll
    for (int i = 0; i < 16; i++) {
        float4 zz = zr[i];
        float4 w1 = __ldg(&((const float4*)lw)[i]);
        float4 w2 = __ldg(&((const float4*)lw)[16 + i]);
        a += zz.x * w1.x + zz.y * w1.y + zz.z * w1.z + zz.w * w1.w;
        b += zz.x * w2.x + zz.y * w2.y + zz.z * w2.z + zz.w * w2.w;
    }
    g_t1[v] = a;
    g_t2[v] = b;
}

__global__ void lp_edge_kernel(const float* __restrict__ lb,
                               float* __restrict__ out, int E)
{
    int e = blockIdx.x * blockDim.x + threadIdx.x;
    if (e >= E) return;
    float p = g_t1[g_src32[e]] + g_t2[g_dst32[e]] + lb[0];
    out[e] = 1.f / (1.f + expf(-p));
}

// ---------------- host launcher ----------------
extern "C" void kernel_launch(void* const* d_in, const int* in_sizes, int n_in,
                              void* d_out, int out_size)
{
    const float* x   = (const float*)d_in[0];
    const void*  ei  = d_in[1];
    const float* ew1 = (const float*)d_in[2];
    const float* eb1 = (const float*)d_in[3];
    const float* ew2 = (const float*)d_in[4];
    const float* eb2 = (const float*)d_in[5];
    const float* efw = (const float*)d_in[6];
    const float* efb = (const float*)d_in[7];
    const float* dw1 = (const float*)d_in[8];
    const float* db1 = (const float*)d_in[9];
    const float* dw2 = (const float*)d_in[10];
    const float* db2 = (const float*)d_in[11];
    const float* dfw = (const float*)d_in[12];
    const float* dfb = (const float*)d_in[13];
    const float* lw  = (const float*)d_in[14];
    const float* lb  = (const float*)d_in[15];

    int N = in_sizes[0] / 128;
    int E = in_sizes[1] / 2;
    if (N > NN) N = NN;
    if (E > EE) E = EE;

    float *bufA, *bufB, *zbuf;
    cudaGetSymbolAddress((void**)&bufA, g_bufA);
    cudaGetSymbolAddress((void**)&bufB, g_bufB);
    cudaGetSymbolAddress((void**)&zbuf, g_z);

    float* xhat  = (float*)d_out;
    float* eprob = (float*)d_out + (size_t)N * 1024;

    int nb = (N + 255) / 256;
    int ebk = (E + 255) / 256;
    int rowTiles = (N + 63) / 64;

    // prep
    detect_kernel<<<1, 32>>>((const long long*)ei);
    convert_kernel<<<ebk, 256>>>(ei, E);
    zero_deg_kernel<<<nb, 256>>>(N);
    hist_kernel<<<ebk, 256>>>(E);
    dinv_kernel<<<nb, 256>>>(N);
    scan_kernel<<<1, 1024>>>(N);
    scatter_kernel<<<ebk, 256>>>(E);

    // encoder
    sgemm_kernel<0><<<dim3(2, rowTiles), 256>>>(x, ew1, nullptr, bufA, N, 128, 128);
    agg_kernel<128, 1><<<(N + 7) / 8, 256>>>(bufA, eb1, bufB, N);
    sgemm_kernel<0><<<dim3(1, rowTiles), 256>>>(bufB, ew2, nullptr, bufA, N, 64, 128);
    agg_kernel<64, 0><<<(N + 7) / 8, 256>>>(bufA, eb2, bufB, N);
    sgemm_kernel<1><<<dim3(1, rowTiles), 256>>>(bufB, efw, efb, zbuf, N, 64, 64);

    // decoder
    sgemm_kernel<0><<<dim3(4, rowTiles), 256>>>(zbuf, dw1, nullptr, bufA, N, 256, 64);
    agg_kernel<256, 1><<<(N + 7) / 8, 256>>>(bufA, db1, bufB, N);
    sgemm_kernel<0><<<dim3(2, rowTiles), 256>>>(bufB, dw2, nullptr, bufA, N, 128, 256);
    agg_kernel<128, 0><<<(N + 7) / 8, 256>>>(bufA, db2, bufB, N);
    sgemm_kernel<1><<<dim3(16, rowTiles), 256>>>(bufB, dfw, dfb, xhat, N, 1024, 128);

    // link predictor
    lp_node_kernel<<<nb, 256>>>(zbuf, lw, N);
    lp_edge_kernel<<<ebk, 256>>>(lb, eprob, E);
}

// round 3
// speedup vs baseline: 1.3308x; 1.3308x over previous
#include <cuda_runtime.h>
#include <cuda_bf16.h>
#include <math.h>

#define NN 50000
#define EE 800000

// ---------------- device scratch ----------------
__device__ float g_bufA[NN * 256];
__device__ float g_bufB[NN * 256];
__device__ float g_z[NN * 64];
__device__ int   g_deg[NN];
__device__ float g_dinv[NN];
__device__ float g_dinv2[NN];
__device__ int   g_rowstart[NN + 1];
__device__ int   g_cursor[NN];
__device__ int   g_src32[EE];
__device__ int   g_dst32[EE];
__device__ int   g_csr_src[EE];
__device__ float g_csr_norm[EE];
__device__ float g_t1[NN];
__device__ float g_t2[NN];
__device__ int   g_flag[1];

// ---------------- f32x2 helpers ----------------
__device__ __forceinline__ void ffma2(unsigned long long& d,
                                      unsigned long long a,
                                      unsigned long long b) {
    asm("fma.rn.f32x2 %0, %1, %2, %0;" : "+l"(d) : "l"(a), "l"(b));
}
__device__ __forceinline__ unsigned long long pack_dup(float v) {
    unsigned long long r;
    unsigned u = __float_as_uint(v);
    asm("mov.b64 %0, {%1, %1};" : "=l"(r) : "r"(u));
    return r;
}
__device__ __forceinline__ void unpack2(unsigned long long v, float& lo, float& hi) {
    unsigned a, b;
    asm("mov.b64 {%0, %1}, %2;" : "=r"(a), "=r"(b) : "l"(v));
    lo = __uint_as_float(a);
    hi = __uint_as_float(b);
}

// ---------------- edge-index dtype detect + convert + hist ----------------
__global__ void detect_kernel(const long long* ei) {
    if (blockIdx.x == 0 && threadIdx.x == 0) {
        int ok = 1;
        for (int i = 0; i < 128; i++) {
            long long v = ei[i];
            if (v < 0 || v >= NN) { ok = 0; break; }
        }
        g_flag[0] = ok;  // 1 = int64, 0 = int32
    }
}

__global__ void zero_deg_kernel(int n) {
    int i = blockIdx.x * blockDim.x + threadIdx.x;
    if (i < n) g_deg[i] = 0;
}

__global__ void convert_hist_kernel(const void* ei, int E) {
    int i = blockIdx.x * blockDim.x + threadIdx.x;
    if (i >= E) return;
    int s, d;
    if (g_flag[0]) {
        const long long* p = (const long long*)ei;
        s = (int)p[i]; d = (int)p[i + E];
    } else {
        const int* p = (const int*)ei;
        s = p[i]; d = p[i + E];
    }
    g_src32[i] = s;
    g_dst32[i] = d;
    atomicAdd(&g_deg[d], 1);
}

__global__ void dinv_kernel(int n) {
    int v = blockIdx.x * blockDim.x + threadIdx.x;
    if (v >= n) return;
    float d = (float)(g_deg[v] + 1);
    float di = rsqrtf(d);
    g_dinv[v]  = di;
    g_dinv2[v] = di * di;
}

// single-block exclusive scan
__global__ void scan_kernel(int n) {
    __shared__ int wsum[32];
    __shared__ int s_carry;
    int tid = threadIdx.x;
    if (tid == 0) s_carry = 0;
    __syncthreads();
    int nch = (n + 1023) / 1024;
    for (int c = 0; c < nch; c++) {
        int i = c * 1024 + tid;
        int v = (i < n) ? g_deg[i] : 0;
        int x = v;
        #pragma unroll
        for (int o = 1; o < 32; o <<= 1) {
            int t = __shfl_up_sync(0xffffffffu, x, o);
            if ((tid & 31) >= o) x += t;
        }
        if ((tid & 31) == 31) wsum[tid >> 5] = x;
        __syncthreads();
        if (tid < 32) {
            int w = wsum[tid];
            #pragma unroll
            for (int o = 1; o < 32; o <<= 1) {
                int t = __shfl_up_sync(0xffffffffu, w, o);
                if (tid >= o) w += t;
            }
            wsum[tid] = w;
        }
        __syncthreads();
        int incl = x + ((tid >= 32) ? wsum[(tid >> 5) - 1] : 0) + s_carry;
        if (i < n) { g_rowstart[i] = incl - v; g_cursor[i] = incl - v; }
        __syncthreads();
        if (tid == 0) s_carry += wsum[31];
        __syncthreads();
    }
    if (tid == 0) g_rowstart[n] = s_carry;
}

__global__ void scatter_kernel(int E) {
    int i = blockIdx.x * blockDim.x + threadIdx.x;
    if (i >= E) return;
    int s = g_src32[i], d = g_dst32[i];
    int pos = atomicAdd(&g_cursor[d], 1);
    g_csr_src[pos]  = s;
    g_csr_norm[pos] = g_dinv[s] * g_dinv[d];
}

// ---------------- SGEMM v2: packed f32x2, 128x64 tile, 256 threads ----------------
#define BM 128
#define BN 64
#define BK 16
#define AS_PITCH 130

template<int FUSE_BIAS, int RELU>
__global__ __launch_bounds__(256) void sgemm2_kernel(
    const float* __restrict__ A, const float* __restrict__ B,
    const float* __restrict__ bias, float* __restrict__ C,
    int M, int Nc, int K)
{
    __shared__ float As[BK * AS_PITCH];                 // As[kk*130 + row]
    __shared__ unsigned long long Bs[BK * BN];          // duplicated {b,b}

    int tid = threadIdx.x;
    int tx = tid & 15;   // cols tx*4..+3
    int ty = tid >> 4;   // rows ty*8..+7
    int bm = blockIdx.y * BM, bn = blockIdx.x * BN;

    int lrow  = tid >> 1;        // A tile row (0..127)
    int lhalf = tid & 1;         // which 8-k half
    int brow  = tid >> 4;        // B tile k row (0..15)
    int bcol  = (tid & 15) * 4;  // B col group

    unsigned long long acc[4][4]; // [col][rowpair]
    #pragma unroll
    for (int c = 0; c < 4; c++)
        #pragma unroll
        for (int j = 0; j < 4; j++) acc[c][j] = 0ULL;

    for (int k0 = 0; k0 < K; k0 += BK) {
        int grow = bm + lrow;
        float4 a0, a1;
        if (grow < M) {
            const float* ap = A + (size_t)grow * K + k0 + lhalf * 8;
            a0 = *(const float4*)ap;
            a1 = *(const float4*)(ap + 4);
        } else {
            a0 = make_float4(0.f, 0.f, 0.f, 0.f); a1 = a0;
        }
        const float* bp = B + (size_t)(k0 + brow) * Nc + bn + bcol;
        float4 bv = *(const float4*)bp;

        __syncthreads();
        int kb = lhalf * 8;
        As[(kb + 0) * AS_PITCH + lrow] = a0.x;
        As[(kb + 1) * AS_PITCH + lrow] = a0.y;
        As[(kb + 2) * AS_PITCH + lrow] = a0.z;
        As[(kb + 3) * AS_PITCH + lrow] = a0.w;
        As[(kb + 4) * AS_PITCH + lrow] = a1.x;
        As[(kb + 5) * AS_PITCH + lrow] = a1.y;
        As[(kb + 6) * AS_PITCH + lrow] = a1.z;
        As[(kb + 7) * AS_PITCH + lrow] = a1.w;
        unsigned long long p0 = pack_dup(bv.x), p1 = pack_dup(bv.y);
        unsigned long long p2 = pack_dup(bv.z), p3 = pack_dup(bv.w);
        *(ulonglong2*)&Bs[brow * BN + bcol]     = make_ulonglong2(p0, p1);
        *(ulonglong2*)&Bs[brow * BN + bcol + 2] = make_ulonglong2(p2, p3);
        __syncthreads();

        #pragma unroll
        for (int kk = 0; kk < BK; kk++) {
            const unsigned long long* arow =
                (const unsigned long long*)(As + kk * AS_PITCH) + ty * 4;
            unsigned long long ap0 = arow[0], ap1 = arow[1];
            unsigned long long ap2 = arow[2], ap3 = arow[3];
            const unsigned long long* br = Bs + kk * BN + tx * 4;
            unsigned long long b0 = br[0], b1 = br[1], b2 = br[2], b3 = br[3];
            ffma2(acc[0][0], ap0, b0); ffma2(acc[0][1], ap1, b0);
            ffma2(acc[0][2], ap2, b0); ffma2(acc[0][3], ap3, b0);
            ffma2(acc[1][0], ap0, b1); ffma2(acc[1][1], ap1, b1);
            ffma2(acc[1][2], ap2, b1); ffma2(acc[1][3], ap3, b1);
            ffma2(acc[2][0], ap0, b2); ffma2(acc[2][1], ap1, b2);
            ffma2(acc[2][2], ap2, b2); ffma2(acc[2][3], ap3, b2);
            ffma2(acc[3][0], ap0, b3); ffma2(acc[3][1], ap1, b3);
            ffma2(acc[3][2], ap2, b3); ffma2(acc[3][3], ap3, b3);
        }
    }

    float bb[4] = {0.f, 0.f, 0.f, 0.f};
    if (FUSE_BIAS) {
        float4 b4 = *(const float4*)(bias + bn + tx * 4);
        bb[0] = b4.x; bb[1] = b4.y; bb[2] = b4.z; bb[3] = b4.w;
    }
    #pragma unroll
    for (int j = 0; j < 4; j++) {
        int r0 = bm + ty * 8 + 2 * j;
        float o0[4], o1[4];
        #pragma unroll
        for (int c = 0; c < 4; c++) {
            unpack2(acc[c][j], o0[c], o1[c]);
            o0[c] += bb[c]; o1[c] += bb[c];
            if (RELU) { o0[c] = fmaxf(o0[c], 0.f); o1[c] = fmaxf(o1[c], 0.f); }
        }
        if (r0 < M)
            *(float4*)&C[(size_t)r0 * Nc + bn + tx * 4] =
                make_float4(o0[0], o0[1], o0[2], o0[3]);
        if (r0 + 1 < M)
            *(float4*)&C[(size_t)(r0 + 1) * Nc + bn + tx * 4] =
                make_float4(o1[0], o1[1], o1[2], o1[3]);
    }
}

// ---------------- CSR gather aggregation (warp per node) ----------------
template<int F, int RELU, int BIAS>
__global__ __launch_bounds__(256) void agg_kernel(
    const float* __restrict__ h, const float* __restrict__ bias,
    float* __restrict__ out, int N)
{
    int gw = (blockIdx.x * blockDim.x + threadIdx.x) >> 5;
    int lane = threadIdx.x & 31;
    if (gw >= N) return;
    constexpr int V = F / 32;
    float acc[V];
    #pragma unroll
    for (int i = 0; i < V; i++) acc[i] = 0.f;
    int e0 = g_rowstart[gw], e1 = g_rowstart[gw + 1];
    const float* base = h + lane * V;
    #pragma unroll 2
    for (int e = e0; e < e1; e++) {
        int s = __ldg(&g_csr_src[e]);
        float w = __ldg(&g_csr_norm[e]);
        const float* r = base + (size_t)s * F;
        if (V == 2) {
            float2 x2 = *(const float2*)r;
            acc[0] += x2.x * w; acc[1] += x2.y * w;
        } else {
            #pragma unroll
            for (int i = 0; i < V; i += 4) {
                float4 x4 = *(const float4*)(r + i);
                acc[i + 0] += x4.x * w; acc[i + 1] += x4.y * w;
                acc[i + 2] += x4.z * w; acc[i + 3] += x4.w * w;
            }
        }
    }
    float sw = g_dinv2[gw];
    const float* sr = base + (size_t)gw * F;
    float* o = out + (size_t)gw * F + lane * V;
    #pragma unroll
    for (int i = 0; i < V; i++) {
        float val = acc[i] + sr[i] * sw;
        if (BIAS) val += bias[lane * V + i];
        if (RELU) val = fmaxf(val, 0.f);
        o[i] = val;
    }
}

// ---------------- link predictor ----------------
__global__ void lp_node_kernel(const float* __restrict__ z,
                               const float* __restrict__ lw, int N)
{
    int v = blockIdx.x * blockDim.x + threadIdx.x;
    if (v >= N) return;
    const float4* zr = (const float4*)(z + (size_t)v * 64);
    float a = 0.f, b = 0.f;
    #pragma unroll
    for (int i = 0; i < 16; i++) {
        float4 zz = zr[i];
        float4 w1 = __ldg(&((const float4*)lw)[i]);
        float4 w2 = __ldg(&((const float4*)lw)[16 + i]);
        a += zz.x * w1.x + zz.y * w1.y + zz.z * w1.z + zz.w * w1.w;
        b += zz.x * w2.x + zz.y * w2.y + zz.z * w2.z + zz.w * w2.w;
    }
    g_t1[v] = a;
    g_t2[v] = b;
}

__global__ void lp_edge_kernel(const float* __restrict__ lb,
                               float* __restrict__ out, int E)
{
    int e = blockIdx.x * blockDim.x + threadIdx.x;
    if (e >= E) return;
    float p = g_t1[g_src32[e]] + g_t2[g_dst32[e]] + lb[0];
    out[e] = 1.f / (1.f + expf(-p));
}

// ---------------- host launcher ----------------
extern "C" void kernel_launch(void* const* d_in, const int* in_sizes, int n_in,
                              void* d_out, int out_size)
{
    const float* x   = (const float*)d_in[0];
    const void*  ei  = d_in[1];
    const float* ew1 = (const float*)d_in[2];
    const float* eb1 = (const float*)d_in[3];
    const float* ew2 = (const float*)d_in[4];
    const float* eb2 = (const float*)d_in[5];
    const float* efw = (const float*)d_in[6];
    const float* efb = (const float*)d_in[7];
    const float* dw1 = (const float*)d_in[8];
    const float* db1 = (const float*)d_in[9];
    const float* dw2 = (const float*)d_in[10];
    const float* db2 = (const float*)d_in[11];
    const float* dfw = (const float*)d_in[12];
    const float* dfb = (const float*)d_in[13];
    const float* lw  = (const float*)d_in[14];
    const float* lb  = (const float*)d_in[15];

    int N = in_sizes[0] / 128;
    int E = in_sizes[1] / 2;
    if (N > NN) N = NN;
    if (E > EE) E = EE;

    float *bufA, *bufB, *zbuf;
    cudaGetSymbolAddress((void**)&bufA, g_bufA);
    cudaGetSymbolAddress((void**)&bufB, g_bufB);
    cudaGetSymbolAddress((void**)&zbuf, g_z);

    float* xhat  = (float*)d_out;
    float* eprob = (float*)d_out + (size_t)N * 1024;

    int nb  = (N + 255) / 256;
    int ebk = (E + 255) / 256;
    int rT  = (N + 127) / 128;
    int aggB = (N + 7) / 8;

    // prep
    detect_kernel<<<1, 32>>>((const long long*)ei);
    zero_deg_kernel<<<nb, 256>>>(N);
    convert_hist_kernel<<<ebk, 256>>>(ei, E);
    dinv_kernel<<<nb, 256>>>(N);
    scan_kernel<<<1, 1024>>>(N);
    scatter_kernel<<<ebk, 256>>>(E);

    // encoder
    sgemm2_kernel<0, 0><<<dim3(2, rT), 256>>>(x, ew1, nullptr, bufA, N, 128, 128);
    agg_kernel<128, 1, 1><<<aggB, 256>>>(bufA, eb1, bufB, N);
    sgemm2_kernel<0, 0><<<dim3(1, rT), 256>>>(bufB, ew2, nullptr, bufA, N, 64, 128);
    agg_kernel<64, 0, 1><<<aggB, 256>>>(bufA, eb2, bufB, N);
    sgemm2_kernel<1, 0><<<dim3(1, rT), 256>>>(bufB, efw, efb, zbuf, N, 64, 64);

    // decoder (aggregate z in 64-dim BEFORE the 64->256 GEMM; linearity)
    agg_kernel<64, 0, 0><<<aggB, 256>>>(zbuf, nullptr, bufA, N);
    sgemm2_kernel<1, 1><<<dim3(4, rT), 256>>>(bufA, dw1, db1, bufB, N, 256, 64);
    sgemm2_kernel<0, 0><<<dim3(2, rT), 256>>>(bufB, dw2, nullptr, bufA, N, 128, 256);
    agg_kernel<128, 0, 1><<<aggB, 256>>>(bufA, db2, bufB, N);
    sgemm2_kernel<1, 0><<<dim3(16, rT), 256>>>(bufB, dfw, dfb, xhat, N, 1024, 128);

    // link predictor
    lp_node_kernel<<<nb, 256>>>(zbuf, lw, N);
    lp_edge_kernel<<<ebk, 256>>>(lb, eprob, E);
}

// round 6
// speedup vs baseline: 2.5123x; 1.8878x over previous
#include <cuda_runtime.h>
#include <cuda_bf16.h>
#include <math.h>
#include <stdint.h>

#define NN 50000
#define EE 800000

// ---------------- device scratch ----------------
__device__ float g_bufA[NN * 256];
__device__ float g_z[NN * 64];
__device__ __nv_bfloat16 g_ahi[NN * 256];
__device__ __nv_bfloat16 g_alo[NN * 256];
__device__ __nv_bfloat16 g_bhi[NN * 256];
__device__ __nv_bfloat16 g_blo[NN * 256];
__device__ __nv_bfloat16 g_wthi[208896];
__device__ __nv_bfloat16 g_wtlo[208896];
__device__ int   g_deg[NN];
__device__ float g_dinv[NN];
__device__ float g_dinv2[NN];
__device__ int   g_rowstart[NN + 1];
__device__ int   g_cursor[NN];
__device__ int   g_src32[EE];
__device__ int   g_dst32[EE];
__device__ int   g_csr_src[EE];
__device__ float g_csr_norm[EE];
__device__ float g_t1[NN];
__device__ float g_t2[NN];
__device__ int   g_flag[1];

// ---------------- prep kernels ----------------
__global__ void detect_kernel(const long long* ei) {
    if (blockIdx.x == 0 && threadIdx.x == 0) {
        int ok = 1;
        for (int i = 0; i < 128; i++) {
            long long v = ei[i];
            if (v < 0 || v >= NN) { ok = 0; break; }
        }
        g_flag[0] = ok;
    }
}

__global__ void zero_deg_kernel(int n) {
    int i = blockIdx.x * blockDim.x + threadIdx.x;
    if (i < n) g_deg[i] = 0;
}

__global__ void convert_hist_kernel(const void* ei, int E) {
    int i = blockIdx.x * blockDim.x + threadIdx.x;
    if (i >= E) return;
    int s, d;
    if (g_flag[0]) {
        const long long* p = (const long long*)ei;
        s = (int)p[i]; d = (int)p[i + E];
    } else {
        const int* p = (const int*)ei;
        s = p[i]; d = p[i + E];
    }
    g_src32[i] = s;
    g_dst32[i] = d;
    atomicAdd(&g_deg[d], 1);
}

__global__ void dinv_kernel(int n) {
    int v = blockIdx.x * blockDim.x + threadIdx.x;
    if (v >= n) return;
    float d = (float)(g_deg[v] + 1);
    float di = rsqrtf(d);
    g_dinv[v]  = di;
    g_dinv2[v] = di * di;
}

__global__ void scan_kernel(int n) {
    __shared__ int wsum[32];
    __shared__ int s_carry;
    int tid = threadIdx.x;
    if (tid == 0) s_carry = 0;
    __syncthreads();
    int nch = (n + 1023) / 1024;
    for (int c = 0; c < nch; c++) {
        int i = c * 1024 + tid;
        int v = (i < n) ? g_deg[i] : 0;
        int x = v;
        #pragma unroll
        for (int o = 1; o < 32; o <<= 1) {
            int t = __shfl_up_sync(0xffffffffu, x, o);
            if ((tid & 31) >= o) x += t;
        }
        if ((tid & 31) == 31) wsum[tid >> 5] = x;
        __syncthreads();
        if (tid < 32) {
            int w = wsum[tid];
            #pragma unroll
            for (int o = 1; o < 32; o <<= 1) {
                int t = __shfl_up_sync(0xffffffffu, w, o);
                if (tid >= o) w += t;
            }
            wsum[tid] = w;
        }
        __syncthreads();
        int incl = x + ((tid >= 32) ? wsum[(tid >> 5) - 1] : 0) + s_carry;
        if (i < n) { g_rowstart[i] = incl - v; g_cursor[i] = incl - v; }
        __syncthreads();
        if (tid == 0) s_carry += wsum[31];
        __syncthreads();
    }
    if (tid == 0) g_rowstart[n] = s_carry;
}

__global__ void scatter_kernel(int E) {
    int i = blockIdx.x * blockDim.x + threadIdx.x;
    if (i >= E) return;
    int s = g_src32[i], d = g_dst32[i];
    int pos = atomicAdd(&g_cursor[d], 1);
    g_csr_src[pos]  = s;
    g_csr_norm[pos] = g_dinv[s] * g_dinv[d];
}

// ---------------- bf16 split helpers ----------------
__device__ __forceinline__ void bf16_split(float v, __nv_bfloat16& h, __nv_bfloat16& l) {
    h = __float2bfloat16(v);
    l = __float2bfloat16(v - __bfloat162float(h));
}

__global__ void split_kernel(const float* __restrict__ X,
                             __nv_bfloat16* __restrict__ hi,
                             __nv_bfloat16* __restrict__ lo, int total) {
    int i = blockIdx.x * blockDim.x + threadIdx.x;
    if (i >= total) return;
    __nv_bfloat16 h, l;
    bf16_split(X[i], h, l);
    hi[i] = h; lo[i] = l;
}

// weight transpose + split: W [K,Nc] fp32 -> Wt hi/lo [Nc,K] bf16
__global__ void wsplit_kernel(const float* __restrict__ W,
                              __nv_bfloat16* __restrict__ hi,
                              __nv_bfloat16* __restrict__ lo, int K, int Nc) {
    int i = blockIdx.x * blockDim.x + threadIdx.x;
    if (i >= K * Nc) return;
    int n = i / K, k = i - n * K;
    __nv_bfloat16 h, l;
    bf16_split(W[(size_t)k * Nc + n], h, l);
    hi[i] = h; lo[i] = l;
}

// ---------------- mma.sync bf16 helper ----------------
__device__ __forceinline__ void mma_bf16(float* c, const uint32_t* a, const uint32_t* b) {
    asm volatile(
        "mma.sync.aligned.m16n8k16.row.col.f32.bf16.bf16.f32 "
        "{%0,%1,%2,%3}, {%4,%5,%6,%7}, {%8,%9}, {%0,%1,%2,%3};"
        : "+f"(c[0]), "+f"(c[1]), "+f"(c[2]), "+f"(c[3])
        : "r"(a[0]), "r"(a[1]), "r"(a[2]), "r"(a[3]), "r"(b[0]), "r"(b[1]));
}

// ---------------- tensor-core GEMM: C[M,Nc] = A[M,K] @ Wt[Nc,K]^T ----------------
// A: bf16 hi/lo [M,K]; Wt: bf16 hi/lo [Nc,K].
// D = Ahi*Bhi + Ahi*Blo + Alo*Bhi, fp32 accumulate.
// CTA: 256 threads (8 warps), tile 128x64, warp tile 32x32 (2x4 m16n8k16).
// K streamed in 64-wide chunks (K always a multiple of 64 here).
#define PITCH 72

template<int BIAS, int RELU, int SPLIT>
__global__ __launch_bounds__(256) void mma_gemm_kernel(
    const __nv_bfloat16* __restrict__ Ahi, const __nv_bfloat16* __restrict__ Alo,
    const __nv_bfloat16* __restrict__ Whi, const __nv_bfloat16* __restrict__ Wlo,
    const float* __restrict__ bias,
    float* __restrict__ Cf,
    __nv_bfloat16* __restrict__ Chi, __nv_bfloat16* __restrict__ Clo,
    int M, int Nc, int K)
{
    __shared__ __nv_bfloat16 sAhi[128 * PITCH];
    __shared__ __nv_bfloat16 sAlo[128 * PITCH];
    __shared__ __nv_bfloat16 sBhi[64 * PITCH];
    __shared__ __nv_bfloat16 sBlo[64 * PITCH];

    int tid  = threadIdx.x;
    int wid  = tid >> 5, lane = tid & 31;
    int wm   = wid & 3;      // 0..3 -> m offset wm*32
    int wn   = wid >> 2;     // 0..1 -> n offset wn*32
    int g    = lane >> 2;    // group id 0..7
    int t    = lane & 3;     // thread-in-group 0..3
    int bm   = blockIdx.y * 128, bn = blockIdx.x * 64;

    float acc[2][4][4];
    #pragma unroll
    for (int i = 0; i < 2; i++)
        #pragma unroll
        for (int j = 0; j < 4; j++)
            #pragma unroll
            for (int r = 0; r < 4; r++) acc[i][j][r] = 0.f;

    int arow = tid >> 1, ahalf = tid & 1;           // A: row, 32-col half
    int btt = tid & 127;
    int brow = btt >> 1, bhalf = btt & 1;           // B: row (n), 32-col half

    for (int kc = 0; kc < K; kc += 64) {
        __syncthreads();
        // load A chunk [128 x 64] hi+lo
        {
            __nv_bfloat16* dH = sAhi + arow * PITCH + ahalf * 32;
            __nv_bfloat16* dL = sAlo + arow * PITCH + ahalf * 32;
            int grow = bm + arow;
            if (grow < M) {
                const uint4* sh = (const uint4*)(Ahi + (size_t)grow * K + kc + ahalf * 32);
                const uint4* sl = (const uint4*)(Alo + (size_t)grow * K + kc + ahalf * 32);
                #pragma unroll
                for (int c = 0; c < 4; c++) {
                    ((uint4*)dH)[c] = sh[c];
                    ((uint4*)dL)[c] = sl[c];
                }
            } else {
                uint4 z = make_uint4(0, 0, 0, 0);
                #pragma unroll
                for (int c = 0; c < 4; c++) { ((uint4*)dH)[c] = z; ((uint4*)dL)[c] = z; }
            }
        }
        // load B chunk [64 x 64]: threads 0-127 hi, 128-255 lo
        {
            const __nv_bfloat16* W = (tid < 128) ? Whi : Wlo;
            __nv_bfloat16* dst = ((tid < 128) ? sBhi : sBlo) + brow * PITCH + bhalf * 32;
            const uint4* src = (const uint4*)(W + (size_t)(bn + brow) * K + kc + bhalf * 32);
            #pragma unroll
            for (int c = 0; c < 4; c++) ((uint4*)dst)[c] = src[c];
        }
        __syncthreads();

        #pragma unroll
        for (int ks = 0; ks < 4; ks++) {
            int kb = ks * 16 + 2 * t;
            // B fragments: 4 n-atoms, hi+lo
            uint32_t bh[4][2], bl[4][2];
            #pragma unroll
            for (int na = 0; na < 4; na++) {
                int n = wn * 32 + na * 8 + g;
                const uint32_t* ph = (const uint32_t*)(sBhi + n * PITCH + kb);
                const uint32_t* pl = (const uint32_t*)(sBlo + n * PITCH + kb);
                bh[na][0] = ph[0]; bh[na][1] = ph[4];
                bl[na][0] = pl[0]; bl[na][1] = pl[4];
            }
            #pragma unroll
            for (int ma = 0; ma < 2; ma++) {
                int r0 = wm * 32 + ma * 16 + g;
                const uint32_t* qh0 = (const uint32_t*)(sAhi + r0 * PITCH + kb);
                const uint32_t* qh8 = (const uint32_t*)(sAhi + (r0 + 8) * PITCH + kb);
                const uint32_t* ql0 = (const uint32_t*)(sAlo + r0 * PITCH + kb);
                const uint32_t* ql8 = (const uint32_t*)(sAlo + (r0 + 8) * PITCH + kb);
                uint32_t ah[4] = {qh0[0], qh8[0], qh0[4], qh8[4]};
                uint32_t al[4] = {ql0[0], ql8[0], ql0[4], ql8[4]};
                #pragma unroll
                for (int na = 0; na < 4; na++) {
                    mma_bf16(acc[ma][na], ah, bh[na]);
                    mma_bf16(acc[ma][na], ah, bl[na]);
                    mma_bf16(acc[ma][na], al, bh[na]);
                }
            }
        }
    }

    // epilogue: c0:(g,2t) c1:(g,2t+1) c2:(g+8,2t) c3:(g+8,2t+1)
    #pragma unroll
    for (int ma = 0; ma < 2; ma++) {
        #pragma unroll
        for (int half = 0; half < 2; half++) {
            int row = bm + wm * 32 + ma * 16 + g + half * 8;
            if (row >= M) continue;
            #pragma unroll
            for (int na = 0; na < 4; na++) {
                int col = bn + wn * 32 + na * 8 + 2 * t;
                float v0 = acc[ma][na][half * 2 + 0];
                float v1 = acc[ma][na][half * 2 + 1];
                if (BIAS) { v0 += __ldg(bias + col); v1 += __ldg(bias + col + 1); }
                if (RELU) { v0 = fmaxf(v0, 0.f); v1 = fmaxf(v1, 0.f); }
                if (SPLIT) {
                    __nv_bfloat16 h0, l0, h1, l1;
                    bf16_split(v0, h0, l0);
                    bf16_split(v1, h1, l1);
                    *(__nv_bfloat162*)(Chi + (size_t)row * Nc + col) = __nv_bfloat162(h0, h1);
                    *(__nv_bfloat162*)(Clo + (size_t)row * Nc + col) = __nv_bfloat162(l0, l1);
                } else {
                    *(float2*)(Cf + (size_t)row * Nc + col) = make_float2(v0, v1);
                }
            }
        }
    }
}

// ---------------- CSR gather aggregation, bf16 hi/lo output ----------------
template<int F, int RELU, int BIAS>
__global__ __launch_bounds__(256) void agg_split_kernel(
    const float* __restrict__ h, const float* __restrict__ bias,
    __nv_bfloat16* __restrict__ outHi, __nv_bfloat16* __restrict__ outLo, int N)
{
    int gw = (blockIdx.x * blockDim.x + threadIdx.x) >> 5;
    int lane = threadIdx.x & 31;
    if (gw >= N) return;
    constexpr int V = F / 32;
    float acc[V];
    #pragma unroll
    for (int i = 0; i < V; i++) acc[i] = 0.f;
    int e0 = g_rowstart[gw], e1 = g_rowstart[gw + 1];
    const float* basep = h + lane * V;
    #pragma unroll 2
    for (int e = e0; e < e1; e++) {
        int s = __ldg(&g_csr_src[e]);
        float w = __ldg(&g_csr_norm[e]);
        const float* r = basep + (size_t)s * F;
        if (V == 2) {
            float2 x2 = *(const float2*)r;
            acc[0] += x2.x * w; acc[1] += x2.y * w;
        } else {
            #pragma unroll
            for (int i = 0; i < V; i += 4) {
                float4 x4 = *(const float4*)(r + i);
                acc[i + 0] += x4.x * w; acc[i + 1] += x4.y * w;
                acc[i + 2] += x4.z * w; acc[i + 3] += x4.w * w;
            }
        }
    }
    float sw = g_dinv2[gw];
    const float* sr = basep + (size_t)gw * F;
    __nv_bfloat16* oh = outHi + (size_t)gw * F + lane * V;
    __nv_bfloat16* ol = outLo + (size_t)gw * F + lane * V;
    #pragma unroll
    for (int i = 0; i < V; i += 2) {
        float v0 = acc[i] + sr[i] * sw;
        float v1 = acc[i + 1] + sr[i + 1] * sw;
        if (BIAS) { v0 += bias[lane * V + i]; v1 += bias[lane * V + i + 1]; }
        if (RELU) { v0 = fmaxf(v0, 0.f); v1 = fmaxf(v1, 0.f); }
        __nv_bfloat16 h0, l0, h1, l1;
        bf16_split(v0, h0, l0);
        bf16_split(v1, h1, l1);
        *(__nv_bfloat162*)(oh + i) = __nv_bfloat162(h0, h1);
        *(__nv_bfloat162*)(ol + i) = __nv_bfloat162(l0, l1);
    }
}

// ---------------- link predictor ----------------
__global__ void lp_node_kernel(const float* __restrict__ z,
                               const float* __restrict__ lw, int N)
{
    int v = blockIdx.x * blockDim.x + threadIdx.x;
    if (v >= N) return;
    const float4* zr = (const float4*)(z + (size_t)v * 64);
    float a = 0.f, b = 0.f;
    #pragma unroll
    for (int i = 0; i < 16; i++) {
        float4 zz = zr[i];
        float4 w1 = __ldg(&((const float4*)lw)[i]);
        float4 w2 = __ldg(&((const float4*)lw)[16 + i]);
        a += zz.x * w1.x + zz.y * w1.y + zz.z * w1.z + zz.w * w1.w;
        b += zz.x * w2.x + zz.y * w2.y + zz.z * w2.z + zz.w * w2.w;
    }
    g_t1[v] = a;
    g_t2[v] = b;
}

__global__ void lp_edge_kernel(const float* __restrict__ lb,
                               float* __restrict__ out, int E)
{
    int e = blockIdx.x * blockDim.x + threadIdx.x;
    if (e >= E) return;
    float p = g_t1[g_src32[e]] + g_t2[g_dst32[e]] + lb[0];
    out[e] = 1.f / (1.f + expf(-p));
}

// ---------------- host launcher ----------------
extern "C" void kernel_launch(void* const* d_in, const int* in_sizes, int n_in,
                              void* d_out, int out_size)
{
    const float* x   = (const float*)d_in[0];
    const void*  ei  = d_in[1];
    const float* ew1 = (const float*)d_in[2];
    const float* eb1 = (const float*)d_in[3];
    const float* ew2 = (const float*)d_in[4];
    const float* eb2 = (const float*)d_in[5];
    const float* efw = (const float*)d_in[6];
    const float* efb = (const float*)d_in[7];
    const float* dw1 = (const float*)d_in[8];
    const float* db1 = (const float*)d_in[9];
    const float* dw2 = (const float*)d_in[10];
    const float* db2 = (const float*)d_in[11];
    const float* dfw = (const float*)d_in[12];
    const float* dfb = (const float*)d_in[13];
    const float* lw  = (const float*)d_in[14];
    const float* lb  = (const float*)d_in[15];

    int N = in_sizes[0] / 128;
    int E = in_sizes[1] / 2;
    if (N > NN) N = NN;
    if (E > EE) E = EE;

    float *bufA, *zbuf;
    __nv_bfloat16 *ahi, *alo, *bhi, *blo, *wthi, *wtlo;
    cudaGetSymbolAddress((void**)&bufA, g_bufA);
    cudaGetSymbolAddress((void**)&zbuf, g_z);
    cudaGetSymbolAddress((void**)&ahi, g_ahi);
    cudaGetSymbolAddress((void**)&alo, g_alo);
    cudaGetSymbolAddress((void**)&bhi, g_bhi);
    cudaGetSymbolAddress((void**)&blo, g_blo);
    cudaGetSymbolAddress((void**)&wthi, g_wthi);
    cudaGetSymbolAddress((void**)&wtlo, g_wtlo);

    const int O_EW1 = 0;
    const int O_EW2 = O_EW1 + 128 * 128;
    const int O_EFW = O_EW2 + 64 * 128;
    const int O_DW1 = O_EFW + 64 * 64;
    const int O_DW2 = O_DW1 + 256 * 64;
    const int O_DFW = O_DW2 + 128 * 256;

    float* xhat  = (float*)d_out;
    float* eprob = (float*)d_out + (size_t)N * 1024;

    int nb  = (N + 255) / 256;
    int ebk = (E + 255) / 256;
    int rT  = (N + 127) / 128;
    int aggB = (N + 7) / 8;

    // prep
    detect_kernel<<<1, 32>>>((const long long*)ei);
    zero_deg_kernel<<<nb, 256>>>(N);
    convert_hist_kernel<<<ebk, 256>>>(ei, E);
    dinv_kernel<<<nb, 256>>>(N);
    scan_kernel<<<1, 1024>>>(N);
    scatter_kernel<<<ebk, 256>>>(E);

    // weight transpose+split (small)
    wsplit_kernel<<<(128*128+255)/256, 256>>>(ew1, wthi + O_EW1, wtlo + O_EW1, 128, 128);
    wsplit_kernel<<<(64*128+255)/256, 256>>>(ew2, wthi + O_EW2, wtlo + O_EW2, 128, 64);
    wsplit_kernel<<<(64*64+255)/256, 256>>>(efw, wthi + O_EFW, wtlo + O_EFW, 64, 64);
    wsplit_kernel<<<(256*64+255)/256, 256>>>(dw1, wthi + O_DW1, wtlo + O_DW1, 64, 256);
    wsplit_kernel<<<(128*256+255)/256, 256>>>(dw2, wthi + O_DW2, wtlo + O_DW2, 256, 128);
    wsplit_kernel<<<(1024*128+255)/256, 256>>>(dfw, wthi + O_DFW, wtlo + O_DFW, 128, 1024);

    // split x
    split_kernel<<<(N * 128 + 255) / 256, 256>>>(x, ahi, alo, N * 128);

    // encoder
    mma_gemm_kernel<0,0,0><<<dim3(2, rT), 256>>>(
        ahi, alo, wthi + O_EW1, wtlo + O_EW1, nullptr, bufA, nullptr, nullptr, N, 128, 128);
    agg_split_kernel<128, 1, 1><<<aggB, 256>>>(bufA, eb1, ahi, alo, N);
    mma_gemm_kernel<0,0,0><<<dim3(1, rT), 256>>>(
        ahi, alo, wthi + O_EW2, wtlo + O_EW2, nullptr, bufA, nullptr, nullptr, N, 64, 128);
    agg_split_kernel<64, 0, 1><<<aggB, 256>>>(bufA, eb2, ahi, alo, N);
    mma_gemm_kernel<1,0,0><<<dim3(1, rT), 256>>>(
        ahi, alo, wthi + O_EFW, wtlo + O_EFW, efb, zbuf, nullptr, nullptr, N, 64, 64);

    // decoder: aggregate z in 64-dim BEFORE 64->256 GEMM (linearity)
    agg_split_kernel<64, 0, 0><<<aggB, 256>>>(zbuf, nullptr, ahi, alo, N);
    mma_gemm_kernel<1,1,1><<<dim3(4, rT), 256>>>(
        ahi, alo, wthi + O_DW1, wtlo + O_DW1, db1, nullptr, bhi, blo, N, 256, 64);
    mma_gemm_kernel<0,0,0><<<dim3(2, rT), 256>>>(
        bhi, blo, wthi + O_DW2, wtlo + O_DW2, nullptr, bufA, nullptr, nullptr, N, 128, 256);
    agg_split_kernel<128, 0, 1><<<aggB, 256>>>(bufA, db2, ahi, alo, N);
    mma_gemm_kernel<1,0,0><<<dim3(16, rT), 256>>>(
        ahi, alo, wthi + O_DFW, wtlo + O_DFW, dfb, xhat, nullptr, nullptr, N, 1024, 128);

    // link predictor
    lp_node_kernel<<<nb, 256>>>(zbuf, lw, N);
    lp_edge_kernel<<<ebk, 256>>>(lb, eprob, E);
}

// round 11
// speedup vs baseline: 2.6558x; 1.0571x over previous
#include <cuda_runtime.h>
#include <cuda_bf16.h>
#include <math.h>
#include <stdint.h>

#define NN 50000
#define EE 800000

// ---------------- device scratch ----------------
__device__ float g_bufA[NN * 256];
__device__ float g_z[NN * 64];
__device__ __nv_bfloat16 g_ahi[NN * 256];
__device__ __nv_bfloat16 g_alo[NN * 256];
__device__ __nv_bfloat16 g_bhi[NN * 256];
__device__ __nv_bfloat16 g_blo[NN * 256];
__device__ __nv_bfloat16 g_wthi[208896];
__device__ __nv_bfloat16 g_wtlo[208896];
__device__ int   g_deg[NN];
__device__ float g_dinv[NN];
__device__ float g_dinv2[NN];
__device__ int   g_rowstart[NN + 1];
__device__ int   g_cursor[NN];
__device__ int   g_src32[EE];
__device__ int   g_dst32[EE];
__device__ int   g_csr_src[EE];
__device__ float g_csr_norm[EE];
__device__ float g_t1[NN];
__device__ float g_t2[NN];
__device__ int   g_flag[1];

// ---------------- prep kernels ----------------
__global__ void detect_kernel(const long long* ei) {
    if (blockIdx.x == 0 && threadIdx.x == 0) {
        int ok = 1;
        for (int i = 0; i < 128; i++) {
            long long v = ei[i];
            if (v < 0 || v >= NN) { ok = 0; break; }
        }
        g_flag[0] = ok;
    }
}

__global__ void zero_deg_kernel(int n) {
    int i = blockIdx.x * blockDim.x + threadIdx.x;
    if (i < n) g_deg[i] = 0;
}

__global__ void convert_hist_kernel(const void* ei, int E) {
    int i = blockIdx.x * blockDim.x + threadIdx.x;
    if (i >= E) return;
    int s, d;
    if (g_flag[0]) {
        const long long* p = (const long long*)ei;
        s = (int)p[i]; d = (int)p[i + E];
    } else {
        const int* p = (const int*)ei;
        s = p[i]; d = p[i + E];
    }
    g_src32[i] = s;
    g_dst32[i] = d;
    atomicAdd(&g_deg[d], 1);
}

// scan + dinv fused (single block)
__global__ void scan_dinv_kernel(int n) {
    __shared__ int wsum[32];
    __shared__ int s_carry;
    int tid = threadIdx.x;
    if (tid == 0) s_carry = 0;
    __syncthreads();
    int nch = (n + 1023) / 1024;
    for (int c = 0; c < nch; c++) {
        int i = c * 1024 + tid;
        int v = (i < n) ? g_deg[i] : 0;
        if (i < n) {
            float d = (float)(v + 1);
            float di = rsqrtf(d);
            g_dinv[i]  = di;
            g_dinv2[i] = di * di;
        }
        int x = v;
        #pragma unroll
        for (int o = 1; o < 32; o <<= 1) {
            int t = __shfl_up_sync(0xffffffffu, x, o);
            if ((tid & 31) >= o) x += t;
        }
        if ((tid & 31) == 31) wsum[tid >> 5] = x;
        __syncthreads();
        if (tid < 32) {
            int w = wsum[tid];
            #pragma unroll
            for (int o = 1; o < 32; o <<= 1) {
                int t = __shfl_up_sync(0xffffffffu, w, o);
                if (tid >= o) w += t;
            }
            wsum[tid] = w;
        }
        __syncthreads();
        int incl = x + ((tid >= 32) ? wsum[(tid >> 5) - 1] : 0) + s_carry;
        if (i < n) { g_rowstart[i] = incl - v; g_cursor[i] = incl - v; }
        __syncthreads();
        if (tid == 0) s_carry += wsum[31];
        __syncthreads();
    }
    if (tid == 0) g_rowstart[n] = s_carry;
}

__global__ void scatter_kernel(int E) {
    int i = blockIdx.x * blockDim.x + threadIdx.x;
    if (i >= E) return;
    int s = g_src32[i], d = g_dst32[i];
    int pos = atomicAdd(&g_cursor[d], 1);
    g_csr_src[pos]  = s;
    g_csr_norm[pos] = g_dinv[s] * g_dinv[d];
}

// ---------------- bf16 split helpers ----------------
__device__ __forceinline__ void bf16_split(float v, __nv_bfloat16& h, __nv_bfloat16& l) {
    h = __float2bfloat16(v);
    l = __float2bfloat16(v - __bfloat162float(h));
}

__global__ void split_kernel(const float* __restrict__ X,
                             __nv_bfloat16* __restrict__ hi,
                             __nv_bfloat16* __restrict__ lo, int total) {
    int i = blockIdx.x * blockDim.x + threadIdx.x;
    if (i >= total) return;
    __nv_bfloat16 h, l;
    bf16_split(X[i], h, l);
    hi[i] = h; lo[i] = l;
}

// all six weight transposes+splits in one launch.
// segment table (elems, K, Nc, out offset) hardcoded.
__global__ void wsplit_all_kernel(const float* __restrict__ ew1,
                                  const float* __restrict__ ew2,
                                  const float* __restrict__ efw,
                                  const float* __restrict__ dw1,
                                  const float* __restrict__ dw2,
                                  const float* __restrict__ dfw,
                                  __nv_bfloat16* __restrict__ hi,
                                  __nv_bfloat16* __restrict__ lo) {
    int i = blockIdx.x * blockDim.x + threadIdx.x;
    if (i >= 208896) return;
    const float* W; int K, Nc, off;
    if (i < 16384)       { W = ew1; K = 128; Nc = 128;  off = 0; }
    else if (i < 24576)  { W = ew2; K = 128; Nc = 64;   off = 16384; }
    else if (i < 28672)  { W = efw; K = 64;  Nc = 64;   off = 24576; }
    else if (i < 45056)  { W = dw1; K = 64;  Nc = 256;  off = 28672; }
    else if (i < 77824)  { W = dw2; K = 256; Nc = 128;  off = 45056; }
    else                 { W = dfw; K = 128; Nc = 1024; off = 77824; }
    int j = i - off;
    int n = j / K, k = j - n * K;
    __nv_bfloat16 h, l;
    bf16_split(W[(size_t)k * Nc + n], h, l);
    hi[i] = h; lo[i] = l;
}

// ---------------- mma.sync helpers ----------------
__device__ __forceinline__ void mma_bf16(float* c, const uint32_t* a, const uint32_t* b) {
    asm volatile(
        "mma.sync.aligned.m16n8k16.row.col.f32.bf16.bf16.f32 "
        "{%0,%1,%2,%3}, {%4,%5,%6,%7}, {%8,%9}, {%0,%1,%2,%3};"
        : "+f"(c[0]), "+f"(c[1]), "+f"(c[2]), "+f"(c[3])
        : "r"(a[0]), "r"(a[1]), "r"(a[2]), "r"(a[3]), "r"(b[0]), "r"(b[1]));
}
__device__ __forceinline__ void ldsm_x4(uint32_t& r0, uint32_t& r1,
                                        uint32_t& r2, uint32_t& r3, uint32_t addr) {
    asm volatile("ldmatrix.sync.aligned.m8n8.x4.shared.b16 {%0,%1,%2,%3}, [%4];"
        : "=r"(r0), "=r"(r1), "=r"(r2), "=r"(r3) : "r"(addr));
}
__device__ __forceinline__ uint32_t smem_u32(const void* p) {
    uint32_t a;
    asm("{ .reg .u64 t; cvta.to.shared.u64 t, %1; cvt.u32.u64 %0, t; }"
        : "=r"(a) : "l"(p));
    return a;
}

// ---------------- tensor-core GEMM: C[M,Nc] = A[M,K] @ Wt[Nc,K]^T ----------------
// ldmatrix fragment loads; tile 128x64, warp tile 32x32, K in 64-chunks.
#define PITCH 72

template<int BIAS, int RELU, int SPLIT, int STREAM>
__global__ __launch_bounds__(256) void mma_gemm_kernel(
    const __nv_bfloat16* __restrict__ Ahi, const __nv_bfloat16* __restrict__ Alo,
    const __nv_bfloat16* __restrict__ Whi, const __nv_bfloat16* __restrict__ Wlo,
    const float* __restrict__ bias,
    float* __restrict__ Cf,
    __nv_bfloat16* __restrict__ Chi, __nv_bfloat16* __restrict__ Clo,
    int M, int Nc, int K)
{
    __shared__ __nv_bfloat16 sAhi[128 * PITCH];
    __shared__ __nv_bfloat16 sAlo[128 * PITCH];
    __shared__ __nv_bfloat16 sBhi[64 * PITCH];
    __shared__ __nv_bfloat16 sBlo[64 * PITCH];

    int tid  = threadIdx.x;
    int wid  = tid >> 5, lane = tid & 31;
    int wm   = wid & 3;
    int wn   = wid >> 2;
    int g    = lane >> 2;
    int t    = lane & 3;
    int bm   = blockIdx.y * 128, bn = blockIdx.x * 64;

    float acc[2][4][4];
    #pragma unroll
    for (int i = 0; i < 2; i++)
        #pragma unroll
        for (int j = 0; j < 4; j++)
            #pragma unroll
            for (int r = 0; r < 4; r++) acc[i][j][r] = 0.f;

    // ldmatrix base addresses (bytes)
    // A: lanes 0-15 -> rows (lane&15), lanes>=16 -> col offset +8 elems
    int aRow0 = wm * 32 + (lane & 15);
    int aColB = (lane & 16) ? 16 : 0;          // bytes
    uint32_t uAhi = smem_u32(sAhi), uAlo = smem_u32(sAlo);
    uint32_t aHi0 = uAhi + (uint32_t)(aRow0 * PITCH * 2 + aColB);
    uint32_t aLo0 = uAlo + (uint32_t)(aRow0 * PITCH * 2 + aColB);
    // B: n = wn*32 + pair*16 + (lane&7) + ((lane&16)?8:0); col = (lane&8)?8:0 elems
    int bRow0 = wn * 32 + (lane & 7) + ((lane & 16) ? 8 : 0);
    int bColB = (lane & 8) ? 16 : 0;
    uint32_t uBhi = smem_u32(sBhi), uBlo = smem_u32(sBlo);
    uint32_t bHi0 = uBhi + (uint32_t)(bRow0 * PITCH * 2 + bColB);
    uint32_t bLo0 = uBlo + (uint32_t)(bRow0 * PITCH * 2 + bColB);
    const uint32_t AROWS16 = 16 * PITCH * 2;   // +16 rows

    int arow = tid >> 1, ahalf = tid & 1;
    int btt = tid & 127;
    int brow = btt >> 1, bhalf = btt & 1;

    for (int kc = 0; kc < K; kc += 64) {
        __syncthreads();
        {
            __nv_bfloat16* dH = sAhi + arow * PITCH + ahalf * 32;
            __nv_bfloat16* dL = sAlo + arow * PITCH + ahalf * 32;
            int grow = bm + arow;
            if (grow < M) {
                const uint4* sh = (const uint4*)(Ahi + (size_t)grow * K + kc + ahalf * 32);
                const uint4* sl = (const uint4*)(Alo + (size_t)grow * K + kc + ahalf * 32);
                #pragma unroll
                for (int c = 0; c < 4; c++) {
                    ((uint4*)dH)[c] = sh[c];
                    ((uint4*)dL)[c] = sl[c];
                }
            } else {
                uint4 z = make_uint4(0, 0, 0, 0);
                #pragma unroll
                for (int c = 0; c < 4; c++) { ((uint4*)dH)[c] = z; ((uint4*)dL)[c] = z; }
            }
        }
        {
            const __nv_bfloat16* W = (tid < 128) ? Whi : Wlo;
            __nv_bfloat16* dst = ((tid < 128) ? sBhi : sBlo) + brow * PITCH + bhalf * 32;
            const uint4* src = (const uint4*)(W + (size_t)(bn + brow) * K + kc + bhalf * 32);
            #pragma unroll
            for (int c = 0; c < 4; c++) ((uint4*)dst)[c] = src[c];
        }
        __syncthreads();

        #pragma unroll
        for (int ks = 0; ks < 4; ks++) {
            uint32_t ofs = ks * 32;           // 16 bf16 = 32 bytes
            uint32_t ah0[4], ah1[4], al0[4], al1[4];
            ldsm_x4(ah0[0], ah0[1], ah0[2], ah0[3], aHi0 + ofs);
            ldsm_x4(ah1[0], ah1[1], ah1[2], ah1[3], aHi0 + AROWS16 + ofs);
            ldsm_x4(al0[0], al0[1], al0[2], al0[3], aLo0 + ofs);
            ldsm_x4(al1[0], al1[1], al1[2], al1[3], aLo0 + AROWS16 + ofs);
            uint32_t bh[4][2], bl[4][2];
            ldsm_x4(bh[0][0], bh[0][1], bh[1][0], bh[1][1], bHi0 + ofs);
            ldsm_x4(bh[2][0], bh[2][1], bh[3][0], bh[3][1], bHi0 + AROWS16 + ofs);
            ldsm_x4(bl[0][0], bl[0][1], bl[1][0], bl[1][1], bLo0 + ofs);
            ldsm_x4(bl[2][0], bl[2][1], bl[3][0], bl[3][1], bLo0 + AROWS16 + ofs);
            #pragma unroll
            for (int na = 0; na < 4; na++) {
                mma_bf16(acc[0][na], ah0, bh[na]);
                mma_bf16(acc[0][na], ah0, bl[na]);
                mma_bf16(acc[0][na], al0, bh[na]);
                mma_bf16(acc[1][na], ah1, bh[na]);
                mma_bf16(acc[1][na], ah1, bl[na]);
                mma_bf16(acc[1][na], al1, bh[na]);
            }
        }
    }

    #pragma unroll
    for (int ma = 0; ma < 2; ma++) {
        #pragma unroll
        for (int half = 0; half < 2; half++) {
            int row = bm + wm * 32 + ma * 16 + g + half * 8;
            if (row >= M) continue;
            #pragma unroll
            for (int na = 0; na < 4; na++) {
                int col = bn + wn * 32 + na * 8 + 2 * t;
                float v0 = acc[ma][na][half * 2 + 0];
                float v1 = acc[ma][na][half * 2 + 1];
                if (BIAS) { v0 += __ldg(bias + col); v1 += __ldg(bias + col + 1); }
                if (RELU) { v0 = fmaxf(v0, 0.f); v1 = fmaxf(v1, 0.f); }
                if (SPLIT) {
                    __nv_bfloat16 h0, l0, h1, l1;
                    bf16_split(v0, h0, l0);
                    bf16_split(v1, h1, l1);
                    *(__nv_bfloat162*)(Chi + (size_t)row * Nc + col) = __nv_bfloat162(h0, h1);
                    *(__nv_bfloat162*)(Clo + (size_t)row * Nc + col) = __nv_bfloat162(l0, l1);
                } else if (STREAM) {
                    asm volatile("st.global.cs.v2.f32 [%0], {%1, %2};"
                        :: "l"(Cf + (size_t)row * Nc + col), "f"(v0), "f"(v1));
                } else {
                    *(float2*)(Cf + (size_t)row * Nc + col) = make_float2(v0, v1);
                }
            }
        }
    }
}

// ---------------- CSR gather aggregation, bf16 hi/lo output ----------------
template<int F, int RELU, int BIAS>
__global__ __launch_bounds__(256) void agg_split_kernel(
    const float* __restrict__ h, const float* __restrict__ bias,
    __nv_bfloat16* __restrict__ outHi, __nv_bfloat16* __restrict__ outLo, int N)
{
    int gw = (blockIdx.x * blockDim.x + threadIdx.x) >> 5;
    int lane = threadIdx.x & 31;
    if (gw >= N) return;
    constexpr int V = F / 32;
    float acc[V];
    #pragma unroll
    for (int i = 0; i < V; i++) acc[i] = 0.f;
    int e0 = g_rowstart[gw], e1 = g_rowstart[gw + 1];
    const float* basep = h + lane * V;
    #pragma unroll 2
    for (int e = e0; e < e1; e++) {
        int s = __ldg(&g_csr_src[e]);
        float w = __ldg(&g_csr_norm[e]);
        const float* r = basep + (size_t)s * F;
        if (V == 2) {
            float2 x2 = *(const float2*)r;
            acc[0] += x2.x * w; acc[1] += x2.y * w;
        } else {
            #pragma unroll
            for (int i = 0; i < V; i += 4) {
                float4 x4 = *(const float4*)(r + i);
                acc[i + 0] += x4.x * w; acc[i + 1] += x4.y * w;
                acc[i + 2] += x4.z * w; acc[i + 3] += x4.w * w;
            }
        }
    }
    float sw = g_dinv2[gw];
    const float* sr = basep + (size_t)gw * F;
    __nv_bfloat16* oh = outHi + (size_t)gw * F + lane * V;
    __nv_bfloat16* ol = outLo + (size_t)gw * F + lane * V;
    #pragma unroll
    for (int i = 0; i < V; i += 2) {
        float v0 = acc[i] + sr[i] * sw;
        float v1 = acc[i + 1] + sr[i + 1] * sw;
        if (BIAS) { v0 += bias[lane * V + i]; v1 += bias[lane * V + i + 1]; }
        if (RELU) { v0 = fmaxf(v0, 0.f); v1 = fmaxf(v1, 0.f); }
        __nv_bfloat16 h0, l0, h1, l1;
        bf16_split(v0, h0, l0);
        bf16_split(v1, h1, l1);
        *(__nv_bfloat162*)(oh + i) = __nv_bfloat162(h0, h1);
        *(__nv_bfloat162*)(ol + i) = __nv_bfloat162(l0, l1);
    }
}

// ---------------- link predictor ----------------
__global__ void lp_node_kernel(const float* __restrict__ z,
                               const float* __restrict__ lw, int N)
{
    int v = blockIdx.x * blockDim.x + threadIdx.x;
    if (v >= N) return;
    const float4* zr = (const float4*)(z + (size_t)v * 64);
    float a = 0.f, b = 0.f;
    #pragma unroll
    for (int i = 0; i < 16; i++) {
        float4 zz = zr[i];
        float4 w1 = __ldg(&((const float4*)lw)[i]);
        float4 w2 = __ldg(&((const float4*)lw)[16 + i]);
        a += zz.x * w1.x + zz.y * w1.y + zz.z * w1.z + zz.w * w1.w;
        b += zz.x * w2.x + zz.y * w2.y + zz.z * w2.z + zz.w * w2.w;
    }
    g_t1[v] = a;
    g_t2[v] = b;
}

__global__ void lp_edge_kernel(const float* __restrict__ lb,
                               float* __restrict__ out, int E)
{
    int e = blockIdx.x * blockDim.x + threadIdx.x;
    if (e >= E) return;
    float p = g_t1[g_src32[e]] + g_t2[g_dst32[e]] + lb[0];
    float v = 1.f / (1.f + expf(-p));
    asm volatile("st.global.cs.f32 [%0], %1;" :: "l"(out + e), "f"(v));
}

// ---------------- host launcher ----------------
extern "C" void kernel_launch(void* const* d_in, const int* in_sizes, int n_in,
                              void* d_out, int out_size)
{
    const float* x   = (const float*)d_in[0];
    const void*  ei  = d_in[1];
    const float* ew1 = (const float*)d_in[2];
    const float* eb1 = (const float*)d_in[3];
    const float* ew2 = (const float*)d_in[4];
    const float* eb2 = (const float*)d_in[5];
    const float* efw = (const float*)d_in[6];
    const float* efb = (const float*)d_in[7];
    const float* dw1 = (const float*)d_in[8];
    const float* db1 = (const float*)d_in[9];
    const float* dw2 = (const float*)d_in[10];
    const float* db2 = (const float*)d_in[11];
    const float* dfw = (const float*)d_in[12];
    const float* dfb = (const float*)d_in[13];
    const float* lw  = (const float*)d_in[14];
    const float* lb  = (const float*)d_in[15];

    int N = in_sizes[0] / 128;
    int E = in_sizes[1] / 2;
    if (N > NN) N = NN;
    if (E > EE) E = EE;

    float *bufA, *zbuf;
    __nv_bfloat16 *ahi, *alo, *bhi, *blo, *wthi, *wtlo;
    cudaGetSymbolAddress((void**)&bufA, g_bufA);
    cudaGetSymbolAddress((void**)&zbuf, g_z);
    cudaGetSymbolAddress((void**)&ahi, g_ahi);
    cudaGetSymbolAddress((void**)&alo, g_alo);
    cudaGetSymbolAddress((void**)&bhi, g_bhi);
    cudaGetSymbolAddress((void**)&blo, g_blo);
    cudaGetSymbolAddress((void**)&wthi, g_wthi);
    cudaGetSymbolAddress((void**)&wtlo, g_wtlo);

    const int O_EW1 = 0;
    const int O_EW2 = O_EW1 + 128 * 128;
    const int O_EFW = O_EW2 + 64 * 128;
    const int O_DW1 = O_EFW + 64 * 64;
    const int O_DW2 = O_DW1 + 256 * 64;
    const int O_DFW = O_DW2 + 128 * 256;

    float* xhat  = (float*)d_out;
    float* eprob = (float*)d_out + (size_t)N * 1024;

    int nb  = (N + 255) / 256;
    int ebk = (E + 255) / 256;
    int rT  = (N + 127) / 128;
    int aggB = (N + 7) / 8;

    // prep
    detect_kernel<<<1, 32>>>((const long long*)ei);
    zero_deg_kernel<<<nb, 256>>>(N);
    convert_hist_kernel<<<ebk, 256>>>(ei, E);
    scan_dinv_kernel<<<1, 1024>>>(N);
    scatter_kernel<<<ebk, 256>>>(E);

    // all weight transposes+splits in one launch
    wsplit_all_kernel<<<(208896 + 255) / 256, 256>>>(ew1, ew2, efw, dw1, dw2, dfw, wthi, wtlo);

    // split x
    split_kernel<<<(N * 128 + 255) / 256, 256>>>(x, ahi, alo, N * 128);

    // encoder
    mma_gemm_kernel<0,0,0,0><<<dim3(2, rT), 256>>>(
        ahi, alo, wthi + O_EW1, wtlo + O_EW1, nullptr, bufA, nullptr, nullptr, N, 128, 128);
    agg_split_kernel<128, 1, 1><<<aggB, 256>>>(bufA, eb1, ahi, alo, N);
    mma_gemm_kernel<0,0,0,0><<<dim3(1, rT), 256>>>(
        ahi, alo, wthi + O_EW2, wtlo + O_EW2, nullptr, bufA, nullptr, nullptr, N, 64, 128);
    agg_split_kernel<64, 0, 1><<<aggB, 256>>>(bufA, eb2, ahi, alo, N);
    mma_gemm_kernel<1,0,0,0><<<dim3(1, rT), 256>>>(
        ahi, alo, wthi + O_EFW, wtlo + O_EFW, efb, zbuf, nullptr, nullptr, N, 64, 64);

    // decoder: aggregate z in 64-dim BEFORE 64->256 GEMM (linearity)
    agg_split_kernel<64, 0, 0><<<aggB, 256>>>(zbuf, nullptr, ahi, alo, N);
    mma_gemm_kernel<1,1,1,0><<<dim3(4, rT), 256>>>(
        ahi, alo, wthi + O_DW1, wtlo + O_DW1, db1, nullptr, bhi, blo, N, 256, 64);
    mma_gemm_kernel<0,0,0,0><<<dim3(2, rT), 256>>>(
        bhi, blo, wthi + O_DW2, wtlo + O_DW2, nullptr, bufA, nullptr, nullptr, N, 128, 256);
    agg_split_kernel<128, 0, 1><<<aggB, 256>>>(bufA, db2, ahi, alo, N);
    mma_gemm_kernel<1,0,0,1><<<dim3(16, rT), 256>>>(
        ahi, alo, wthi + O_DFW, wtlo + O_DFW, dfb, xhat, nullptr, nullptr, N, 1024, 128);

    // link predictor
    lp_node_kernel<<<nb, 256>>>(zbuf, lw, N);
    lp_edge_kernel<<<ebk, 256>>>(lb, eprob, E);
}

// round 13
// speedup vs baseline: 2.9511x; 1.1112x over previous
#include <cuda_runtime.h>
#include <cuda_bf16.h>
#include <math.h>
#include <stdint.h>

#define NN 50000
#define EE 800000
#define SCAN_B 196   // ceil(50000/256)

// ---------------- device scratch ----------------
__device__ float g_bufA[NN * 256];
__device__ float g_z[NN * 64];
__device__ __nv_bfloat16 g_ahi[NN * 256];
__device__ __nv_bfloat16 g_alo[NN * 256];
__device__ __nv_bfloat16 g_bhi[NN * 256];
__device__ __nv_bfloat16 g_blo[NN * 256];
__device__ __nv_bfloat16 g_wthi[208896];
__device__ __nv_bfloat16 g_wtlo[208896];
__device__ int   g_deg[NN];
__device__ float g_dinv[NN];
__device__ float g_dinv2[NN];
__device__ int   g_rowstart[NN + 1];
__device__ int   g_cursor[NN];
__device__ int   g_bsum[256];
__device__ int   g_boff[256];
__device__ int   g_src32[EE];
__device__ int   g_dst32[EE];
__device__ int   g_csr_src[EE];
__device__ float g_csr_norm[EE];
__device__ float g_t1[NN];
__device__ float g_t2[NN];
__device__ int   g_flag[1];

// ---------------- prep kernels ----------------
__global__ void detect_kernel(const long long* ei) {
    if (blockIdx.x == 0 && threadIdx.x == 0) {
        int ok = 1;
        for (int i = 0; i < 128; i++) {
            long long v = ei[i];
            if (v < 0 || v >= NN) { ok = 0; break; }
        }
        g_flag[0] = ok;
    }
}

__global__ void convert_hist_kernel(const void* ei, int E) {
    int i = blockIdx.x * blockDim.x + threadIdx.x;
    if (i >= E) return;
    int s, d;
    if (g_flag[0]) {
        const long long* p = (const long long*)ei;
        s = (int)p[i]; d = (int)p[i + E];
    } else {
        const int* p = (const int*)ei;
        s = p[i]; d = p[i + E];
    }
    g_src32[i] = s;
    g_dst32[i] = d;
    atomicAdd(&g_deg[d], 1);
}

// ---- multi-block scan: pass1 (block-local exclusive scan + dinv) ----
__global__ __launch_bounds__(256) void scan_p1_kernel(int n) {
    __shared__ int wsum[8];
    int tid = threadIdx.x;
    int i = blockIdx.x * 256 + tid;
    int v = (i < n) ? g_deg[i] : 0;
    if (i < n) {
        float di = rsqrtf((float)(v + 1));
        g_dinv[i]  = di;
        g_dinv2[i] = di * di;
    }
    int x = v;
    #pragma unroll
    for (int o = 1; o < 32; o <<= 1) {
        int t = __shfl_up_sync(0xffffffffu, x, o);
        if ((tid & 31) >= o) x += t;
    }
    if ((tid & 31) == 31) wsum[tid >> 5] = x;
    __syncthreads();
    if (tid < 8) {
        int w = wsum[tid];
        #pragma unroll
        for (int o = 1; o < 8; o <<= 1) {
            int t = __shfl_up_sync(0xffu, w, o);
            if (tid >= o) w += t;
        }
        wsum[tid] = w;
    }
    __syncthreads();
    int incl = x + ((tid >= 32) ? wsum[(tid >> 5) - 1] : 0);
    if (i < n) g_rowstart[i] = incl - v;   // block-local exclusive
    if (tid == 255) g_bsum[blockIdx.x] = incl;
}

// ---- pass2: single block scans the block sums (nb <= 256) ----
__global__ __launch_bounds__(256) void scan_p2_kernel(int nb, int n) {
    __shared__ int wsum[8];
    int tid = threadIdx.x;
    int v = (tid < nb) ? g_bsum[tid] : 0;
    int x = v;
    #pragma unroll
    for (int o = 1; o < 32; o <<= 1) {
        int t = __shfl_up_sync(0xffffffffu, x, o);
        if ((tid & 31) >= o) x += t;
    }
    if ((tid & 31) == 31) wsum[tid >> 5] = x;
    __syncthreads();
    if (tid < 8) {
        int w = wsum[tid];
        #pragma unroll
        for (int o = 1; o < 8; o <<= 1) {
            int t = __shfl_up_sync(0xffu, w, o);
            if (tid >= o) w += t;
        }
        wsum[tid] = w;
    }
    __syncthreads();
    int incl = x + ((tid >= 32) ? wsum[(tid >> 5) - 1] : 0);
    if (tid < nb) g_boff[tid] = incl - v;
    if (tid == 255) g_rowstart[n] = incl;  // total edges
}

// ---- pass3: apply block offsets, init cursor ----
__global__ __launch_bounds__(256) void scan_p3_kernel(int n) {
    int i = blockIdx.x * 256 + threadIdx.x;
    if (i >= n) return;
    int r = g_rowstart[i] + g_boff[blockIdx.x];
    g_rowstart[i] = r;
    g_cursor[i]   = r;
}

__global__ void scatter_kernel(int E) {
    int i = blockIdx.x * blockDim.x + threadIdx.x;
    if (i >= E) return;
    int s = g_src32[i], d = g_dst32[i];
    int pos = atomicAdd(&g_cursor[d], 1);
    g_csr_src[pos]  = s;
    g_csr_norm[pos] = g_dinv[s] * g_dinv[d];
}

// ---------------- bf16 split helpers ----------------
__device__ __forceinline__ void bf16_split(float v, __nv_bfloat16& h, __nv_bfloat16& l) {
    h = __float2bfloat16(v);
    l = __float2bfloat16(v - __bfloat162float(h));
}

__global__ void split_kernel(const float* __restrict__ X,
                             __nv_bfloat16* __restrict__ hi,
                             __nv_bfloat16* __restrict__ lo, int total) {
    int i = blockIdx.x * blockDim.x + threadIdx.x;
    if (i >= total) return;
    __nv_bfloat16 h, l;
    bf16_split(X[i], h, l);
    hi[i] = h; lo[i] = l;
}

__global__ void wsplit_all_kernel(const float* __restrict__ ew1,
                                  const float* __restrict__ ew2,
                                  const float* __restrict__ efw,
                                  const float* __restrict__ dw1,
                                  const float* __restrict__ dw2,
                                  const float* __restrict__ dfw,
                                  __nv_bfloat16* __restrict__ hi,
                                  __nv_bfloat16* __restrict__ lo) {
    int i = blockIdx.x * blockDim.x + threadIdx.x;
    if (i >= 208896) return;
    const float* W; int K, Nc, off;
    if (i < 16384)       { W = ew1; K = 128; Nc = 128;  off = 0; }
    else if (i < 24576)  { W = ew2; K = 128; Nc = 64;   off = 16384; }
    else if (i < 28672)  { W = efw; K = 64;  Nc = 64;   off = 24576; }
    else if (i < 45056)  { W = dw1; K = 64;  Nc = 256;  off = 28672; }
    else if (i < 77824)  { W = dw2; K = 256; Nc = 128;  off = 45056; }
    else                 { W = dfw; K = 128; Nc = 1024; off = 77824; }
    int j = i - off;
    int n = j / K, k = j - n * K;
    __nv_bfloat16 h, l;
    bf16_split(W[(size_t)k * Nc + n], h, l);
    hi[i] = h; lo[i] = l;
}

// ---------------- mma.sync helpers ----------------
__device__ __forceinline__ void mma_bf16(float* c, const uint32_t* a, const uint32_t* b) {
    asm volatile(
        "mma.sync.aligned.m16n8k16.row.col.f32.bf16.bf16.f32 "
        "{%0,%1,%2,%3}, {%4,%5,%6,%7}, {%8,%9}, {%0,%1,%2,%3};"
        : "+f"(c[0]), "+f"(c[1]), "+f"(c[2]), "+f"(c[3])
        : "r"(a[0]), "r"(a[1]), "r"(a[2]), "r"(a[3]), "r"(b[0]), "r"(b[1]));
}
__device__ __forceinline__ void ldsm_x4(uint32_t& r0, uint32_t& r1,
                                        uint32_t& r2, uint32_t& r3, uint32_t addr) {
    asm volatile("ldmatrix.sync.aligned.m8n8.x4.shared.b16 {%0,%1,%2,%3}, [%4];"
        : "=r"(r0), "=r"(r1), "=r"(r2), "=r"(r3) : "r"(addr));
}
__device__ __forceinline__ uint32_t smem_u32(const void* p) {
    uint32_t a;
    asm("{ .reg .u64 t; cvta.to.shared.u64 t, %1; cvt.u32.u64 %0, t; }"
        : "=r"(a) : "l"(p));
    return a;
}

// ---------------- tensor-core GEMM ----------------
#define PITCH 72

template<int BIAS, int RELU, int SPLIT, int STREAM>
__global__ __launch_bounds__(256) void mma_gemm_kernel(
    const __nv_bfloat16* __restrict__ Ahi, const __nv_bfloat16* __restrict__ Alo,
    const __nv_bfloat16* __restrict__ Whi, const __nv_bfloat16* __restrict__ Wlo,
    const float* __restrict__ bias,
    float* __restrict__ Cf,
    __nv_bfloat16* __restrict__ Chi, __nv_bfloat16* __restrict__ Clo,
    int M, int Nc, int K)
{
    __shared__ __nv_bfloat16 sAhi[128 * PITCH];
    __shared__ __nv_bfloat16 sAlo[128 * PITCH];
    __shared__ __nv_bfloat16 sBhi[64 * PITCH];
    __shared__ __nv_bfloat16 sBlo[64 * PITCH];

    int tid  = threadIdx.x;
    int wid  = tid >> 5, lane = tid & 31;
    int wm   = wid & 3;
    int wn   = wid >> 2;
    int g    = lane >> 2;
    int t    = lane & 3;
    int bm   = blockIdx.y * 128, bn = blockIdx.x * 64;

    float acc[2][4][4];
    #pragma unroll
    for (int i = 0; i < 2; i++)
        #pragma unroll
        for (int j = 0; j < 4; j++)
            #pragma unroll
            for (int r = 0; r < 4; r++) acc[i][j][r] = 0.f;

    int aRow0 = wm * 32 + (lane & 15);
    int aColB = (lane & 16) ? 16 : 0;
    uint32_t uAhi = smem_u32(sAhi), uAlo = smem_u32(sAlo);
    uint32_t aHi0 = uAhi + (uint32_t)(aRow0 * PITCH * 2 + aColB);
    uint32_t aLo0 = uAlo + (uint32_t)(aRow0 * PITCH * 2 + aColB);
    int bRow0 = wn * 32 + (lane & 7) + ((lane & 16) ? 8 : 0);
    int bColB = (lane & 8) ? 16 : 0;
    uint32_t uBhi = smem_u32(sBhi), uBlo = smem_u32(sBlo);
    uint32_t bHi0 = uBhi + (uint32_t)(bRow0 * PITCH * 2 + bColB);
    uint32_t bLo0 = uBlo + (uint32_t)(bRow0 * PITCH * 2 + bColB);
    const uint32_t AROWS16 = 16 * PITCH * 2;

    int arow = tid >> 1, ahalf = tid & 1;
    int btt = tid & 127;
    int brow = btt >> 1, bhalf = btt & 1;

    for (int kc = 0; kc < K; kc += 64) {
        __syncthreads();
        {
            __nv_bfloat16* dH = sAhi + arow * PITCH + ahalf * 32;
            __nv_bfloat16* dL = sAlo + arow * PITCH + ahalf * 32;
            int grow = bm + arow;
            if (grow < M) {
                const uint4* sh = (const uint4*)(Ahi + (size_t)grow * K + kc + ahalf * 32);
                const uint4* sl = (const uint4*)(Alo + (size_t)grow * K + kc + ahalf * 32);
                #pragma unroll
                for (int c = 0; c < 4; c++) {
                    ((uint4*)dH)[c] = sh[c];
                    ((uint4*)dL)[c] = sl[c];
                }
            } else {
                uint4 z = make_uint4(0, 0, 0, 0);
                #pragma unroll
                for (int c = 0; c < 4; c++) { ((uint4*)dH)[c] = z; ((uint4*)dL)[c] = z; }
            }
        }
        {
            const __nv_bfloat16* W = (tid < 128) ? Whi : Wlo;
            __nv_bfloat16* dst = ((tid < 128) ? sBhi : sBlo) + brow * PITCH + bhalf * 32;
            const uint4* src = (const uint4*)(W + (size_t)(bn + brow) * K + kc + bhalf * 32);
            #pragma unroll
            for (int c = 0; c < 4; c++) ((uint4*)dst)[c] = src[c];
        }
        __syncthreads();

        #pragma unroll
        for (int ks = 0; ks < 4; ks++) {
            uint32_t ofs = ks * 32;
            uint32_t ah0[4], ah1[4], al0[4], al1[4];
            ldsm_x4(ah0[0], ah0[1], ah0[2], ah0[3], aHi0 + ofs);
            ldsm_x4(ah1[0], ah1[1], ah1[2], ah1[3], aHi0 + AROWS16 + ofs);
            ldsm_x4(al0[0], al0[1], al0[2], al0[3], aLo0 + ofs);
            ldsm_x4(al1[0], al1[1], al1[2], al1[3], aLo0 + AROWS16 + ofs);
            uint32_t bh[4][2], bl[4][2];
            ldsm_x4(bh[0][0], bh[0][1], bh[1][0], bh[1][1], bHi0 + ofs);
            ldsm_x4(bh[2][0], bh[2][1], bh[3][0], bh[3][1], bHi0 + AROWS16 + ofs);
            ldsm_x4(bl[0][0], bl[0][1], bl[1][0], bl[1][1], bLo0 + ofs);
            ldsm_x4(bl[2][0], bl[2][1], bl[3][0], bl[3][1], bLo0 + AROWS16 + ofs);
            #pragma unroll
            for (int na = 0; na < 4; na++) {
                mma_bf16(acc[0][na], ah0, bh[na]);
                mma_bf16(acc[0][na], ah0, bl[na]);
                mma_bf16(acc[0][na], al0, bh[na]);
                mma_bf16(acc[1][na], ah1, bh[na]);
                mma_bf16(acc[1][na], ah1, bl[na]);
                mma_bf16(acc[1][na], al1, bh[na]);
            }
        }
    }

    #pragma unroll
    for (int ma = 0; ma < 2; ma++) {
        #pragma unroll
        for (int half = 0; half < 2; half++) {
            int row = bm + wm * 32 + ma * 16 + g + half * 8;
            if (row >= M) continue;
            #pragma unroll
            for (int na = 0; na < 4; na++) {
                int col = bn + wn * 32 + na * 8 + 2 * t;
                float v0 = acc[ma][na][half * 2 + 0];
                float v1 = acc[ma][na][half * 2 + 1];
                if (BIAS) { v0 += __ldg(bias + col); v1 += __ldg(bias + col + 1); }
                if (RELU) { v0 = fmaxf(v0, 0.f); v1 = fmaxf(v1, 0.f); }
                if (SPLIT) {
                    __nv_bfloat16 h0, l0, h1, l1;
                    bf16_split(v0, h0, l0);
                    bf16_split(v1, h1, l1);
                    *(__nv_bfloat162*)(Chi + (size_t)row * Nc + col) = __nv_bfloat162(h0, h1);
                    *(__nv_bfloat162*)(Clo + (size_t)row * Nc + col) = __nv_bfloat162(l0, l1);
                } else if (STREAM) {
                    asm volatile("st.global.cs.v2.f32 [%0], {%1, %2};"
                        :: "l"(Cf + (size_t)row * Nc + col), "f"(v0), "f"(v1));
                } else {
                    *(float2*)(Cf + (size_t)row * Nc + col) = make_float2(v0, v1);
                }
            }
        }
    }
}

// ---------------- CSR gather aggregation, bf16 hi/lo output ----------------
template<int F, int RELU, int BIAS>
__global__ __launch_bounds__(256) void agg_split_kernel(
    const float* __restrict__ h, const float* __restrict__ bias,
    __nv_bfloat16* __restrict__ outHi, __nv_bfloat16* __restrict__ outLo, int N)
{
    int gw = (blockIdx.x * blockDim.x + threadIdx.x) >> 5;
    int lane = threadIdx.x & 31;
    if (gw >= N) return;
    constexpr int V = F / 32;
    float acc[V];
    #pragma unroll
    for (int i = 0; i < V; i++) acc[i] = 0.f;
    int e0 = g_rowstart[gw], e1 = g_rowstart[gw + 1];
    const float* basep = h + lane * V;
    #pragma unroll 2
    for (int e = e0; e < e1; e++) {
        int s = __ldg(&g_csr_src[e]);
        float w = __ldg(&g_csr_norm[e]);
        const float* r = basep + (size_t)s * F;
        if (V == 2) {
            float2 x2 = *(const float2*)r;
            acc[0] += x2.x * w; acc[1] += x2.y * w;
        } else {
            #pragma unroll
            for (int i = 0; i < V; i += 4) {
                float4 x4 = *(const float4*)(r + i);
                acc[i + 0] += x4.x * w; acc[i + 1] += x4.y * w;
                acc[i + 2] += x4.z * w; acc[i + 3] += x4.w * w;
            }
        }
    }
    float sw = g_dinv2[gw];
    const float* sr = basep + (size_t)gw * F;
    __nv_bfloat16* oh = outHi + (size_t)gw * F + lane * V;
    __nv_bfloat16* ol = outLo + (size_t)gw * F + lane * V;
    #pragma unroll
    for (int i = 0; i < V; i += 2) {
        float v0 = acc[i] + sr[i] * sw;
        float v1 = acc[i + 1] + sr[i + 1] * sw;
        if (BIAS) { v0 += bias[lane * V + i]; v1 += bias[lane * V + i + 1]; }
        if (RELU) { v0 = fmaxf(v0, 0.f); v1 = fmaxf(v1, 0.f); }
        __nv_bfloat16 h0, l0, h1, l1;
        bf16_split(v0, h0, l0);
        bf16_split(v1, h1, l1);
        *(__nv_bfloat162*)(oh + i) = __nv_bfloat162(h0, h1);
        *(__nv_bfloat162*)(ol + i) = __nv_bfloat162(l0, l1);
    }
}

// ---------------- link predictor ----------------
__global__ void lp_node_kernel(const float* __restrict__ z,
                               const float* __restrict__ lw, int N)
{
    int v = blockIdx.x * blockDim.x + threadIdx.x;
    if (v >= N) return;
    const float4* zr = (const float4*)(z + (size_t)v * 64);
    float a = 0.f, b = 0.f;
    #pragma unroll
    for (int i = 0; i < 16; i++) {
        float4 zz = zr[i];
        float4 w1 = __ldg(&((const float4*)lw)[i]);
        float4 w2 = __ldg(&((const float4*)lw)[16 + i]);
        a += zz.x * w1.x + zz.y * w1.y + zz.z * w1.z + zz.w * w1.w;
        b += zz.x * w2.x + zz.y * w2.y + zz.z * w2.z + zz.w * w2.w;
    }
    g_t1[v] = a;
    g_t2[v] = b;
}

__global__ void lp_edge_kernel(const float* __restrict__ lb,
                               float* __restrict__ out, int E)
{
    int e = blockIdx.x * blockDim.x + threadIdx.x;
    if (e >= E) return;
    float p = g_t1[g_src32[e]] + g_t2[g_dst32[e]] + lb[0];
    float v = 1.f / (1.f + expf(-p));
    asm volatile("st.global.cs.f32 [%0], %1;" :: "l"(out + e), "f"(v));
}

// ---------------- host launcher ----------------
extern "C" void kernel_launch(void* const* d_in, const int* in_sizes, int n_in,
                              void* d_out, int out_size)
{
    const float* x   = (const float*)d_in[0];
    const void*  ei  = d_in[1];
    const float* ew1 = (const float*)d_in[2];
    const float* eb1 = (const float*)d_in[3];
    const float* ew2 = (const float*)d_in[4];
    const float* eb2 = (const float*)d_in[5];
    const float* efw = (const float*)d_in[6];
    const float* efb = (const float*)d_in[7];
    const float* dw1 = (const float*)d_in[8];
    const float* db1 = (const float*)d_in[9];
    const float* dw2 = (const float*)d_in[10];
    const float* db2 = (const float*)d_in[11];
    const float* dfw = (const float*)d_in[12];
    const float* dfb = (const float*)d_in[13];
    const float* lw  = (const float*)d_in[14];
    const float* lb  = (const float*)d_in[15];

    int N = in_sizes[0] / 128;
    int E = in_sizes[1] / 2;
    if (N > NN) N = NN;
    if (E > EE) E = EE;

    float *bufA, *zbuf;
    __nv_bfloat16 *ahi, *alo, *bhi, *blo, *wthi, *wtlo;
    int* degp;
    cudaGetSymbolAddress((void**)&bufA, g_bufA);
    cudaGetSymbolAddress((void**)&zbuf, g_z);
    cudaGetSymbolAddress((void**)&ahi, g_ahi);
    cudaGetSymbolAddress((void**)&alo, g_alo);
    cudaGetSymbolAddress((void**)&bhi, g_bhi);
    cudaGetSymbolAddress((void**)&blo, g_blo);
    cudaGetSymbolAddress((void**)&wthi, g_wthi);
    cudaGetSymbolAddress((void**)&wtlo, g_wtlo);
    cudaGetSymbolAddress((void**)&degp, g_deg);

    const int O_EW1 = 0;
    const int O_EW2 = O_EW1 + 128 * 128;
    const int O_EFW = O_EW2 + 64 * 128;
    const int O_DW1 = O_EFW + 64 * 64;
    const int O_DW2 = O_DW1 + 256 * 64;
    const int O_DFW = O_DW2 + 128 * 256;

    float* xhat  = (float*)d_out;
    float* eprob = (float*)d_out + (size_t)N * 1024;

    int nb  = (N + 255) / 256;
    int ebk = (E + 255) / 256;
    int rT  = (N + 127) / 128;
    int aggB = (N + 7) / 8;

    // persistent side streams + events (created once, outside any capture)
    static cudaStream_t sPrep = nullptr, sLp = nullptr;
    static cudaEvent_t evRoot, evPrep, evZ, evLp;
    if (!sPrep) {
        cudaStreamCreateWithFlags(&sPrep, cudaStreamNonBlocking);
        cudaStreamCreateWithFlags(&sLp, cudaStreamNonBlocking);
        cudaEventCreateWithFlags(&evRoot, cudaEventDisableTiming);
        cudaEventCreateWithFlags(&evPrep, cudaEventDisableTiming);
        cudaEventCreateWithFlags(&evZ, cudaEventDisableTiming);
        cudaEventCreateWithFlags(&evLp, cudaEventDisableTiming);
    }

    // fork side stream for edge prep
    cudaEventRecord(evRoot, 0);
    cudaStreamWaitEvent(sPrep, evRoot, 0);

    // ---- side stream: edge prep chain ----
    detect_kernel<<<1, 32, 0, sPrep>>>((const long long*)ei);
    cudaMemsetAsync(degp, 0, (size_t)N * sizeof(int), sPrep);
    convert_hist_kernel<<<ebk, 256, 0, sPrep>>>(ei, E);
    scan_p1_kernel<<<nb, 256, 0, sPrep>>>(N);
    scan_p2_kernel<<<1, 256, 0, sPrep>>>(nb, N);
    scan_p3_kernel<<<nb, 256, 0, sPrep>>>(N);
    scatter_kernel<<<ebk, 256, 0, sPrep>>>(E);
    cudaEventRecord(evPrep, sPrep);

    // ---- main stream: splits + encoder GEMM1 (independent of edges) ----
    wsplit_all_kernel<<<(208896 + 255) / 256, 256>>>(ew1, ew2, efw, dw1, dw2, dfw, wthi, wtlo);
    split_kernel<<<(N * 128 + 255) / 256, 256>>>(x, ahi, alo, N * 128);
    mma_gemm_kernel<0,0,0,0><<<dim3(2, rT), 256>>>(
        ahi, alo, wthi + O_EW1, wtlo + O_EW1, nullptr, bufA, nullptr, nullptr, N, 128, 128);

    // join: aggregations need CSR
    cudaStreamWaitEvent(0, evPrep, 0);

    agg_split_kernel<128, 1, 1><<<aggB, 256>>>(bufA, eb1, ahi, alo, N);
    mma_gemm_kernel<0,0,0,0><<<dim3(1, rT), 256>>>(
        ahi, alo, wthi + O_EW2, wtlo + O_EW2, nullptr, bufA, nullptr, nullptr, N, 64, 128);
    agg_split_kernel<64, 0, 1><<<aggB, 256>>>(bufA, eb2, ahi, alo, N);
    mma_gemm_kernel<1,0,0,0><<<dim3(1, rT), 256>>>(
        ahi, alo, wthi + O_EFW, wtlo + O_EFW, efb, zbuf, nullptr, nullptr, N, 64, 64);

    // fork link predictor (z ready), overlaps decoder
    cudaEventRecord(evZ, 0);
    cudaStreamWaitEvent(sLp, evZ, 0);
    lp_node_kernel<<<nb, 256, 0, sLp>>>(zbuf, lw, N);
    lp_edge_kernel<<<ebk, 256, 0, sLp>>>(lb, eprob, E);
    cudaEventRecord(evLp, sLp);

    // ---- main stream: decoder ----
    agg_split_kernel<64, 0, 0><<<aggB, 256>>>(zbuf, nullptr, ahi, alo, N);
    mma_gemm_kernel<1,1,1,0><<<dim3(4, rT), 256>>>(
        ahi, alo, wthi + O_DW1, wtlo + O_DW1, db1, nullptr, bhi, blo, N, 256, 64);
    mma_gemm_kernel<0,0,0,0><<<dim3(2, rT), 256>>>(
        bhi, blo, wthi + O_DW2, wtlo + O_DW2, nullptr, bufA, nullptr, nullptr, N, 128, 256);
    agg_split_kernel<128, 0, 1><<<aggB, 256>>>(bufA, db2, ahi, alo, N);
    mma_gemm_kernel<1,0,0,1><<<dim3(16, rT), 256>>>(
        ahi, alo, wthi + O_DFW, wtlo + O_DFW, dfb, xhat, nullptr, nullptr, N, 1024, 128);

    // join link predictor
    cudaStreamWaitEvent(0, evLp, 0);
}

// round 14
// speedup vs baseline: 3.0642x; 1.0383x over previous
#include <cuda_runtime.h>
#include <cuda_bf16.h>
#include <cuda_fp16.h>
#include <math.h>
#include <stdint.h>

#define NN 50000
#define EE 800000

// ---------------- device scratch ----------------
__device__ float g_bufA[NN * 256];
__device__ float g_z[NN * 64];
__device__ __nv_bfloat16 g_ahi[NN * 256];
__device__ __nv_bfloat16 g_alo[NN * 256];
__device__ __nv_bfloat16 g_bhi[NN * 256];
__device__ __nv_bfloat16 g_blo[NN * 256];
__device__ __nv_bfloat16 g_wthi[208896];
__device__ __nv_bfloat16 g_wtlo[208896];
__device__ int   g_deg[NN];
__device__ float g_dinv[NN];
__device__ float g_dinv2[NN];
__device__ int   g_rowstart[NN + 1];
__device__ int   g_cursor[NN];
__device__ int   g_bsum[256];
__device__ int   g_boff[256];
__device__ int   g_src32[EE];
__device__ int   g_dst32[EE];
__device__ int   g_csr_src[EE];
__device__ float g_csr_norm[EE];
__device__ float g_t1[NN];
__device__ float g_t2[NN];
__device__ int   g_flag[1];

// ---------------- prep kernels ----------------
__global__ void detect_kernel(const long long* ei) {
    if (blockIdx.x == 0 && threadIdx.x == 0) {
        int ok = 1;
        for (int i = 0; i < 128; i++) {
            long long v = ei[i];
            if (v < 0 || v >= NN) { ok = 0; break; }
        }
        g_flag[0] = ok;
    }
}

__global__ void convert_hist_kernel(const void* ei, int E) {
    int i = blockIdx.x * blockDim.x + threadIdx.x;
    if (i >= E) return;
    int s, d;
    if (g_flag[0]) {
        const long long* p = (const long long*)ei;
        s = (int)p[i]; d = (int)p[i + E];
    } else {
        const int* p = (const int*)ei;
        s = p[i]; d = p[i + E];
    }
    g_src32[i] = s;
    g_dst32[i] = d;
    atomicAdd(&g_deg[d], 1);
}

__global__ __launch_bounds__(256) void scan_p1_kernel(int n) {
    __shared__ int wsum[8];
    int tid = threadIdx.x;
    int i = blockIdx.x * 256 + tid;
    int v = (i < n) ? g_deg[i] : 0;
    if (i < n) {
        float di = rsqrtf((float)(v + 1));
        g_dinv[i]  = di;
        g_dinv2[i] = di * di;
    }
    int x = v;
    #pragma unroll
    for (int o = 1; o < 32; o <<= 1) {
        int t = __shfl_up_sync(0xffffffffu, x, o);
        if ((tid & 31) >= o) x += t;
    }
    if ((tid & 31) == 31) wsum[tid >> 5] = x;
    __syncthreads();
    if (tid < 8) {
        int w = wsum[tid];
        #pragma unroll
        for (int o = 1; o < 8; o <<= 1) {
            int t = __shfl_up_sync(0xffu, w, o);
            if (tid >= o) w += t;
        }
        wsum[tid] = w;
    }
    __syncthreads();
    int incl = x + ((tid >= 32) ? wsum[(tid >> 5) - 1] : 0);
    if (i < n) g_rowstart[i] = incl - v;
    if (tid == 255) g_bsum[blockIdx.x] = incl;
}

__global__ __launch_bounds__(256) void scan_p2_kernel(int nb, int n) {
    __shared__ int wsum[8];
    int tid = threadIdx.x;
    int v = (tid < nb) ? g_bsum[tid] : 0;
    int x = v;
    #pragma unroll
    for (int o = 1; o < 32; o <<= 1) {
        int t = __shfl_up_sync(0xffffffffu, x, o);
        if ((tid & 31) >= o) x += t;
    }
    if ((tid & 31) == 31) wsum[tid >> 5] = x;
    __syncthreads();
    if (tid < 8) {
        int w = wsum[tid];
        #pragma unroll
        for (int o = 1; o < 8; o <<= 1) {
            int t = __shfl_up_sync(0xffu, w, o);
            if (tid >= o) w += t;
        }
        wsum[tid] = w;
    }
    __syncthreads();
    int incl = x + ((tid >= 32) ? wsum[(tid >> 5) - 1] : 0);
    if (tid < nb) g_boff[tid] = incl - v;
    if (tid == 255) g_rowstart[n] = incl;
}

__global__ __launch_bounds__(256) void scan_p3_kernel(int n) {
    int i = blockIdx.x * 256 + threadIdx.x;
    if (i >= n) return;
    int r = g_rowstart[i] + g_boff[blockIdx.x];
    g_rowstart[i] = r;
    g_cursor[i]   = r;
}

__global__ void scatter_kernel(int E) {
    int i = blockIdx.x * blockDim.x + threadIdx.x;
    if (i >= E) return;
    int s = g_src32[i], d = g_dst32[i];
    int pos = atomicAdd(&g_cursor[d], 1);
    g_csr_src[pos]  = s;
    g_csr_norm[pos] = g_dinv[s] * g_dinv[d];
}

// ---------------- split helpers ----------------
__device__ __forceinline__ void bf16_split(float v, __nv_bfloat16& h, __nv_bfloat16& l) {
    h = __float2bfloat16(v);
    l = __float2bfloat16(v - __bfloat162float(h));
}
__device__ __forceinline__ void f16_split(float v, __half& h, __half& l) {
    h = __float2half_rn(v);
    l = __float2half_rn(v - __half2float(h));
}

__global__ void split_kernel(const float* __restrict__ X,
                             __nv_bfloat16* __restrict__ hi,
                             __nv_bfloat16* __restrict__ lo, int total) {
    int i = blockIdx.x * blockDim.x + threadIdx.x;
    if (i >= total) return;
    __nv_bfloat16 h, l;
    bf16_split(X[i], h, l);
    hi[i] = h; lo[i] = l;
}

// weight transposes+splits for the 5 bf16 GEMMs (77824 elems)
__global__ void wsplit_all_kernel(const float* __restrict__ ew1,
                                  const float* __restrict__ ew2,
                                  const float* __restrict__ efw,
                                  const float* __restrict__ dw1,
                                  const float* __restrict__ dw2,
                                  __nv_bfloat16* __restrict__ hi,
                                  __nv_bfloat16* __restrict__ lo) {
    int i = blockIdx.x * blockDim.x + threadIdx.x;
    if (i >= 77824) return;
    const float* W; int K, Nc, off;
    if (i < 16384)       { W = ew1; K = 128; Nc = 128;  off = 0; }
    else if (i < 24576)  { W = ew2; K = 128; Nc = 64;   off = 16384; }
    else if (i < 28672)  { W = efw; K = 64;  Nc = 64;   off = 24576; }
    else if (i < 45056)  { W = dw1; K = 64;  Nc = 256;  off = 28672; }
    else                 { W = dw2; K = 256; Nc = 128;  off = 45056; }
    int j = i - off;
    int n = j / K, k = j - n * K;
    __nv_bfloat16 h, l;
    bf16_split(W[(size_t)k * Nc + n], h, l);
    hi[i] = h; lo[i] = l;
}

// dfw: transpose + single fp16 (final GEMM uses 2-product fp16)
__global__ void wsplit_dfw_f16_kernel(const float* __restrict__ W,
                                      __half* __restrict__ out) {
    int i = blockIdx.x * blockDim.x + threadIdx.x;   // [Nc=1024][K=128]
    if (i >= 1024 * 128) return;
    int n = i >> 7, k = i & 127;
    out[i] = __float2half_rn(W[(size_t)k * 1024 + n]);
}

// ---------------- mma.sync helpers ----------------
__device__ __forceinline__ void mma_bf16(float* c, const uint32_t* a, const uint32_t* b) {
    asm volatile(
        "mma.sync.aligned.m16n8k16.row.col.f32.bf16.bf16.f32 "
        "{%0,%1,%2,%3}, {%4,%5,%6,%7}, {%8,%9}, {%0,%1,%2,%3};"
        : "+f"(c[0]), "+f"(c[1]), "+f"(c[2]), "+f"(c[3])
        : "r"(a[0]), "r"(a[1]), "r"(a[2]), "r"(a[3]), "r"(b[0]), "r"(b[1]));
}
__device__ __forceinline__ void mma_f16(float* c, const uint32_t* a, const uint32_t* b) {
    asm volatile(
        "mma.sync.aligned.m16n8k16.row.col.f32.f16.f16.f32 "
        "{%0,%1,%2,%3}, {%4,%5,%6,%7}, {%8,%9}, {%0,%1,%2,%3};"
        : "+f"(c[0]), "+f"(c[1]), "+f"(c[2]), "+f"(c[3])
        : "r"(a[0]), "r"(a[1]), "r"(a[2]), "r"(a[3]), "r"(b[0]), "r"(b[1]));
}
__device__ __forceinline__ void ldsm_x4(uint32_t& r0, uint32_t& r1,
                                        uint32_t& r2, uint32_t& r3, uint32_t addr) {
    asm volatile("ldmatrix.sync.aligned.m8n8.x4.shared.b16 {%0,%1,%2,%3}, [%4];"
        : "=r"(r0), "=r"(r1), "=r"(r2), "=r"(r3) : "r"(addr));
}
__device__ __forceinline__ void ldsm_x2(uint32_t& r0, uint32_t& r1, uint32_t addr) {
    asm volatile("ldmatrix.sync.aligned.m8n8.x2.shared.b16 {%0,%1}, [%2];"
        : "=r"(r0), "=r"(r1) : "r"(addr));
}
__device__ __forceinline__ uint32_t smem_u32(const void* p) {
    uint32_t a;
    asm("{ .reg .u64 t; cvta.to.shared.u64 t, %1; cvt.u32.u64 %0, t; }"
        : "=r"(a) : "l"(p));
    return a;
}

#define PITCH 72

// ---------------- bf16 3-product GEMM (encoder/middle layers) ----------------
template<int BIAS, int RELU, int SPLIT>
__global__ __launch_bounds__(256) void mma_gemm_kernel(
    const __nv_bfloat16* __restrict__ Ahi, const __nv_bfloat16* __restrict__ Alo,
    const __nv_bfloat16* __restrict__ Whi, const __nv_bfloat16* __restrict__ Wlo,
    const float* __restrict__ bias,
    float* __restrict__ Cf,
    __nv_bfloat16* __restrict__ Chi, __nv_bfloat16* __restrict__ Clo,
    int M, int Nc, int K)
{
    __shared__ __nv_bfloat16 sAhi[128 * PITCH];
    __shared__ __nv_bfloat16 sAlo[128 * PITCH];
    __shared__ __nv_bfloat16 sBhi[64 * PITCH];
    __shared__ __nv_bfloat16 sBlo[64 * PITCH];

    int tid  = threadIdx.x;
    int wid  = tid >> 5, lane = tid & 31;
    int wm   = wid & 3;
    int wn   = wid >> 2;
    int g    = lane >> 2;
    int t    = lane & 3;
    int bm   = blockIdx.y * 128, bn = blockIdx.x * 64;

    float acc[2][4][4];
    #pragma unroll
    for (int i = 0; i < 2; i++)
        #pragma unroll
        for (int j = 0; j < 4; j++)
            #pragma unroll
            for (int r = 0; r < 4; r++) acc[i][j][r] = 0.f;

    int aRow0 = wm * 32 + (lane & 15);
    int aColB = (lane & 16) ? 16 : 0;
    uint32_t uAhi = smem_u32(sAhi), uAlo = smem_u32(sAlo);
    uint32_t aHi0 = uAhi + (uint32_t)(aRow0 * PITCH * 2 + aColB);
    uint32_t aLo0 = uAlo + (uint32_t)(aRow0 * PITCH * 2 + aColB);
    int bRow0 = wn * 32 + (lane & 7) + ((lane & 16) ? 8 : 0);
    int bColB = (lane & 8) ? 16 : 0;
    uint32_t uBhi = smem_u32(sBhi), uBlo = smem_u32(sBlo);
    uint32_t bHi0 = uBhi + (uint32_t)(bRow0 * PITCH * 2 + bColB);
    uint32_t bLo0 = uBlo + (uint32_t)(bRow0 * PITCH * 2 + bColB);
    const uint32_t AROWS16 = 16 * PITCH * 2;

    int arow = tid >> 1, ahalf = tid & 1;
    int btt = tid & 127;
    int brow = btt >> 1, bhalf = btt & 1;

    for (int kc = 0; kc < K; kc += 64) {
        __syncthreads();
        {
            __nv_bfloat16* dH = sAhi + arow * PITCH + ahalf * 32;
            __nv_bfloat16* dL = sAlo + arow * PITCH + ahalf * 32;
            int grow = bm + arow;
            if (grow < M) {
                const uint4* sh = (const uint4*)(Ahi + (size_t)grow * K + kc + ahalf * 32);
                const uint4* sl = (const uint4*)(Alo + (size_t)grow * K + kc + ahalf * 32);
                #pragma unroll
                for (int c = 0; c < 4; c++) {
                    ((uint4*)dH)[c] = sh[c];
                    ((uint4*)dL)[c] = sl[c];
                }
            } else {
                uint4 z = make_uint4(0, 0, 0, 0);
                #pragma unroll
                for (int c = 0; c < 4; c++) { ((uint4*)dH)[c] = z; ((uint4*)dL)[c] = z; }
            }
        }
        {
            const __nv_bfloat16* W = (tid < 128) ? Whi : Wlo;
            __nv_bfloat16* dst = ((tid < 128) ? sBhi : sBlo) + brow * PITCH + bhalf * 32;
            const uint4* src = (const uint4*)(W + (size_t)(bn + brow) * K + kc + bhalf * 32);
            #pragma unroll
            for (int c = 0; c < 4; c++) ((uint4*)dst)[c] = src[c];
        }
        __syncthreads();

        #pragma unroll
        for (int ks = 0; ks < 4; ks++) {
            uint32_t ofs = ks * 32;
            uint32_t ah0[4], ah1[4], al0[4], al1[4];
            ldsm_x4(ah0[0], ah0[1], ah0[2], ah0[3], aHi0 + ofs);
            ldsm_x4(ah1[0], ah1[1], ah1[2], ah1[3], aHi0 + AROWS16 + ofs);
            ldsm_x4(al0[0], al0[1], al0[2], al0[3], aLo0 + ofs);
            ldsm_x4(al1[0], al1[1], al1[2], al1[3], aLo0 + AROWS16 + ofs);
            uint32_t bh[4][2], bl[4][2];
            ldsm_x4(bh[0][0], bh[0][1], bh[1][0], bh[1][1], bHi0 + ofs);
            ldsm_x4(bh[2][0], bh[2][1], bh[3][0], bh[3][1], bHi0 + AROWS16 + ofs);
            ldsm_x4(bl[0][0], bl[0][1], bl[1][0], bl[1][1], bLo0 + ofs);
            ldsm_x4(bl[2][0], bl[2][1], bl[3][0], bl[3][1], bLo0 + AROWS16 + ofs);
            #pragma unroll
            for (int na = 0; na < 4; na++) {
                mma_bf16(acc[0][na], ah0, bh[na]);
                mma_bf16(acc[0][na], ah0, bl[na]);
                mma_bf16(acc[0][na], al0, bh[na]);
                mma_bf16(acc[1][na], ah1, bh[na]);
                mma_bf16(acc[1][na], ah1, bl[na]);
                mma_bf16(acc[1][na], al1, bh[na]);
            }
        }
    }

    #pragma unroll
    for (int ma = 0; ma < 2; ma++) {
        #pragma unroll
        for (int half = 0; half < 2; half++) {
            int row = bm + wm * 32 + ma * 16 + g + half * 8;
            if (row >= M) continue;
            #pragma unroll
            for (int na = 0; na < 4; na++) {
                int col = bn + wn * 32 + na * 8 + 2 * t;
                float v0 = acc[ma][na][half * 2 + 0];
                float v1 = acc[ma][na][half * 2 + 1];
                if (BIAS) { v0 += __ldg(bias + col); v1 += __ldg(bias + col + 1); }
                if (RELU) { v0 = fmaxf(v0, 0.f); v1 = fmaxf(v1, 0.f); }
                if (SPLIT) {
                    __nv_bfloat16 h0, l0, h1, l1;
                    bf16_split(v0, h0, l0);
                    bf16_split(v1, h1, l1);
                    *(__nv_bfloat162*)(Chi + (size_t)row * Nc + col) = __nv_bfloat162(h0, h1);
                    *(__nv_bfloat162*)(Clo + (size_t)row * Nc + col) = __nv_bfloat162(l0, l1);
                } else {
                    *(float2*)(Cf + (size_t)row * Nc + col) = make_float2(v0, v1);
                }
            }
        }
    }
}

// ---------------- fp16 2-product GEMM (final output layer) ----------------
__global__ __launch_bounds__(256) void mma_gemm_f16_kernel(
    const __half* __restrict__ Ahi, const __half* __restrict__ Alo,
    const __half* __restrict__ W,
    const float* __restrict__ bias,
    float* __restrict__ Cf,
    int M, int Nc, int K)
{
    __shared__ __half sAhi[128 * PITCH];
    __shared__ __half sAlo[128 * PITCH];
    __shared__ __half sB[64 * PITCH];

    int tid  = threadIdx.x;
    int wid  = tid >> 5, lane = tid & 31;
    int wm   = wid & 3;
    int wn   = wid >> 2;
    int g    = lane >> 2;
    int t    = lane & 3;
    int bm   = blockIdx.y * 128, bn = blockIdx.x * 64;

    float acc[2][4][4];
    #pragma unroll
    for (int i = 0; i < 2; i++)
        #pragma unroll
        for (int j = 0; j < 4; j++)
            #pragma unroll
            for (int r = 0; r < 4; r++) acc[i][j][r] = 0.f;

    int aRow0 = wm * 32 + (lane & 15);
    int aColB = (lane & 16) ? 16 : 0;
    uint32_t uAhi = smem_u32(sAhi), uAlo = smem_u32(sAlo);
    uint32_t aHi0 = uAhi + (uint32_t)(aRow0 * PITCH * 2 + aColB);
    uint32_t aLo0 = uAlo + (uint32_t)(aRow0 * PITCH * 2 + aColB);
    int bRow0 = wn * 32 + (lane & 7) + ((lane & 16) ? 8 : 0);
    int bColB = (lane & 8) ? 16 : 0;
    uint32_t uB = smem_u32(sB);
    uint32_t bB0 = uB + (uint32_t)(bRow0 * PITCH * 2 + bColB);
    const uint32_t AROWS16 = 16 * PITCH * 2;

    int arow = tid >> 1, ahalf = tid & 1;
    int btt = tid & 127;
    int brow = btt >> 1, bhalf = btt & 1;

    for (int kc = 0; kc < K; kc += 64) {
        __syncthreads();
        {
            __half* dH = sAhi + arow * PITCH + ahalf * 32;
            __half* dL = sAlo + arow * PITCH + ahalf * 32;
            int grow = bm + arow;
            if (grow < M) {
                const uint4* sh = (const uint4*)(Ahi + (size_t)grow * K + kc + ahalf * 32);
                const uint4* sl = (const uint4*)(Alo + (size_t)grow * K + kc + ahalf * 32);
                #pragma unroll
                for (int c = 0; c < 4; c++) {
                    ((uint4*)dH)[c] = sh[c];
                    ((uint4*)dL)[c] = sl[c];
                }
            } else {
                uint4 z = make_uint4(0, 0, 0, 0);
                #pragma unroll
                for (int c = 0; c < 4; c++) { ((uint4*)dH)[c] = z; ((uint4*)dL)[c] = z; }
            }
        }
        if (tid < 128) {
            __half* dst = sB + brow * PITCH + bhalf * 32;
            const uint4* src = (const uint4*)(W + (size_t)(bn + brow) * K + kc + bhalf * 32);
            #pragma unroll
            for (int c = 0; c < 4; c++) ((uint4*)dst)[c] = src[c];
        }
        __syncthreads();

        #pragma unroll
        for (int ks = 0; ks < 4; ks++) {
            uint32_t ofs = ks * 32;
            uint32_t ah0[4], ah1[4], al0[4], al1[4];
            ldsm_x4(ah0[0], ah0[1], ah0[2], ah0[3], aHi0 + ofs);
            ldsm_x4(ah1[0], ah1[1], ah1[2], ah1[3], aHi0 + AROWS16 + ofs);
            ldsm_x4(al0[0], al0[1], al0[2], al0[3], aLo0 + ofs);
            ldsm_x4(al1[0], al1[1], al1[2], al1[3], aLo0 + AROWS16 + ofs);
            uint32_t b[4][2];
            ldsm_x4(b[0][0], b[0][1], b[1][0], b[1][1], bB0 + ofs);
            ldsm_x4(b[2][0], b[2][1], b[3][0], b[3][1], bB0 + AROWS16 + ofs);
            #pragma unroll
            for (int na = 0; na < 4; na++) {
                mma_f16(acc[0][na], ah0, b[na]);
                mma_f16(acc[0][na], al0, b[na]);
                mma_f16(acc[1][na], ah1, b[na]);
                mma_f16(acc[1][na], al1, b[na]);
            }
        }
    }

    #pragma unroll
    for (int ma = 0; ma < 2; ma++) {
        #pragma unroll
        for (int half = 0; half < 2; half++) {
            int row = bm + wm * 32 + ma * 16 + g + half * 8;
            if (row >= M) continue;
            #pragma unroll
            for (int na = 0; na < 4; na++) {
                int col = bn + wn * 32 + na * 8 + 2 * t;
                float v0 = acc[ma][na][half * 2 + 0] + __ldg(bias + col);
                float v1 = acc[ma][na][half * 2 + 1] + __ldg(bias + col + 1);
                asm volatile("st.global.cs.v2.f32 [%0], {%1, %2};"
                    :: "l"(Cf + (size_t)row * Nc + col), "f"(v0), "f"(v1));
            }
        }
    }
}

// ---------------- CSR gather aggregation, bf16 hi/lo output ----------------
template<int F, int RELU, int BIAS>
__global__ __launch_bounds__(256) void agg_split_kernel(
    const float* __restrict__ h, const float* __restrict__ bias,
    __nv_bfloat16* __restrict__ outHi, __nv_bfloat16* __restrict__ outLo, int N)
{
    int gw = (blockIdx.x * blockDim.x + threadIdx.x) >> 5;
    int lane = threadIdx.x & 31;
    if (gw >= N) return;
    constexpr int V = F / 32;
    float acc[V];
    #pragma unroll
    for (int i = 0; i < V; i++) acc[i] = 0.f;
    int e0 = g_rowstart[gw], e1 = g_rowstart[gw + 1];
    const float* basep = h + lane * V;
    #pragma unroll 2
    for (int e = e0; e < e1; e++) {
        int s = __ldg(&g_csr_src[e]);
        float w = __ldg(&g_csr_norm[e]);
        const float* r = basep + (size_t)s * F;
        if (V == 2) {
            float2 x2 = *(const float2*)r;
            acc[0] += x2.x * w; acc[1] += x2.y * w;
        } else {
            #pragma unroll
            for (int i = 0; i < V; i += 4) {
                float4 x4 = *(const float4*)(r + i);
                acc[i + 0] += x4.x * w; acc[i + 1] += x4.y * w;
                acc[i + 2] += x4.z * w; acc[i + 3] += x4.w * w;
            }
        }
    }
    float sw = g_dinv2[gw];
    const float* sr = basep + (size_t)gw * F;
    __nv_bfloat16* oh = outHi + (size_t)gw * F + lane * V;
    __nv_bfloat16* ol = outLo + (size_t)gw * F + lane * V;
    #pragma unroll
    for (int i = 0; i < V; i += 2) {
        float v0 = acc[i] + sr[i] * sw;
        float v1 = acc[i + 1] + sr[i + 1] * sw;
        if (BIAS) { v0 += bias[lane * V + i]; v1 += bias[lane * V + i + 1]; }
        if (RELU) { v0 = fmaxf(v0, 0.f); v1 = fmaxf(v1, 0.f); }
        __nv_bfloat16 h0, l0, h1, l1;
        bf16_split(v0, h0, l0);
        bf16_split(v1, h1, l1);
        *(__nv_bfloat162*)(oh + i) = __nv_bfloat162(h0, h1);
        *(__nv_bfloat162*)(ol + i) = __nv_bfloat162(l0, l1);
    }
}

// fp16 output variant (feeds the fp16 final GEMM)
template<int F>
__global__ __launch_bounds__(256) void agg_split_f16_kernel(
    const float* __restrict__ h, const float* __restrict__ bias,
    __half* __restrict__ outHi, __half* __restrict__ outLo, int N)
{
    int gw = (blockIdx.x * blockDim.x + threadIdx.x) >> 5;
    int lane = threadIdx.x & 31;
    if (gw >= N) return;
    constexpr int V = F / 32;
    float acc[V];
    #pragma unroll
    for (int i = 0; i < V; i++) acc[i] = 0.f;
    int e0 = g_rowstart[gw], e1 = g_rowstart[gw + 1];
    const float* basep = h + lane * V;
    #pragma unroll 2
    for (int e = e0; e < e1; e++) {
        int s = __ldg(&g_csr_src[e]);
        float w = __ldg(&g_csr_norm[e]);
        const float* r = basep + (size_t)s * F;
        #pragma unroll
        for (int i = 0; i < V; i += 4) {
            float4 x4 = *(const float4*)(r + i);
            acc[i + 0] += x4.x * w; acc[i + 1] += x4.y * w;
            acc[i + 2] += x4.z * w; acc[i + 3] += x4.w * w;
        }
    }
    float sw = g_dinv2[gw];
    const float* sr = basep + (size_t)gw * F;
    __half* oh = outHi + (size_t)gw * F + lane * V;
    __half* ol = outLo + (size_t)gw * F + lane * V;
    #pragma unroll
    for (int i = 0; i < V; i += 2) {
        float v0 = acc[i] + sr[i] * sw + bias[lane * V + i];
        float v1 = acc[i + 1] + sr[i + 1] * sw + bias[lane * V + i + 1];
        __half h0, l0, h1, l1;
        f16_split(v0, h0, l0);
        f16_split(v1, h1, l1);
        *(__half2*)(oh + i) = __half2(h0, h1);
        *(__half2*)(ol + i) = __half2(l0, l1);
    }
}

// ---------------- link predictor ----------------
__global__ void lp_node_kernel(const float* __restrict__ z,
                               const float* __restrict__ lw, int N)
{
    int v = blockIdx.x * blockDim.x + threadIdx.x;
    if (v >= N) return;
    const float4* zr = (const float4*)(z + (size_t)v * 64);
    float a = 0.f, b = 0.f;
    #pragma unroll
    for (int i = 0; i < 16; i++) {
        float4 zz = zr[i];
        float4 w1 = __ldg(&((const float4*)lw)[i]);
        float4 w2 = __ldg(&((const float4*)lw)[16 + i]);
        a += zz.x * w1.x + zz.y * w1.y + zz.z * w1.z + zz.w * w1.w;
        b += zz.x * w2.x + zz.y * w2.y + zz.z * w2.z + zz.w * w2.w;
    }
    g_t1[v] = a;
    g_t2[v] = b;
}

__global__ void lp_edge_kernel(const float* __restrict__ lb,
                               float* __restrict__ out, int E)
{
    int e = blockIdx.x * blockDim.x + threadIdx.x;
    if (e >= E) return;
    float p = g_t1[g_src32[e]] + g_t2[g_dst32[e]] + lb[0];
    float v = 1.f / (1.f + expf(-p));
    asm volatile("st.global.cs.f32 [%0], %1;" :: "l"(out + e), "f"(v));
}

// ---------------- host launcher ----------------
extern "C" void kernel_launch(void* const* d_in, const int* in_sizes, int n_in,
                              void* d_out, int out_size)
{
    const float* x   = (const float*)d_in[0];
    const void*  ei  = d_in[1];
    const float* ew1 = (const float*)d_in[2];
    const float* eb1 = (const float*)d_in[3];
    const float* ew2 = (const float*)d_in[4];
    const float* eb2 = (const float*)d_in[5];
    const float* efw = (const float*)d_in[6];
    const float* efb = (const float*)d_in[7];
    const float* dw1 = (const float*)d_in[8];
    const float* db1 = (const float*)d_in[9];
    const float* dw2 = (const float*)d_in[10];
    const float* db2 = (const float*)d_in[11];
    const float* dfw = (const float*)d_in[12];
    const float* dfb = (const float*)d_in[13];
    const float* lw  = (const float*)d_in[14];
    const float* lb  = (const float*)d_in[15];

    int N = in_sizes[0] / 128;
    int E = in_sizes[1] / 2;
    if (N > NN) N = NN;
    if (E > EE) E = EE;

    float *bufA, *zbuf;
    __nv_bfloat16 *ahi, *alo, *bhi, *blo, *wthi, *wtlo;
    int* degp;
    cudaGetSymbolAddress((void**)&bufA, g_bufA);
    cudaGetSymbolAddress((void**)&zbuf, g_z);
    cudaGetSymbolAddress((void**)&ahi, g_ahi);
    cudaGetSymbolAddress((void**)&alo, g_alo);
    cudaGetSymbolAddress((void**)&bhi, g_bhi);
    cudaGetSymbolAddress((void**)&blo, g_blo);
    cudaGetSymbolAddress((void**)&wthi, g_wthi);
    cudaGetSymbolAddress((void**)&wtlo, g_wtlo);
    cudaGetSymbolAddress((void**)&degp, g_deg);

    const int O_EW1 = 0;
    const int O_EW2 = O_EW1 + 128 * 128;
    const int O_EFW = O_EW2 + 64 * 128;
    const int O_DW1 = O_EFW + 64 * 64;
    const int O_DW2 = O_DW1 + 256 * 64;
    const int O_DFW = O_DW2 + 128 * 256;   // fp16 region (reinterpreted)

    float* xhat  = (float*)d_out;
    float* eprob = (float*)d_out + (size_t)N * 1024;

    int nb  = (N + 255) / 256;
    int ebk = (E + 255) / 256;
    int rT  = (N + 127) / 128;
    int aggB = (N + 7) / 8;

    static cudaStream_t sPrep = nullptr, sLp = nullptr;
    static cudaEvent_t evRoot, evPrep, evZ, evLp;
    if (!sPrep) {
        cudaStreamCreateWithFlags(&sPrep, cudaStreamNonBlocking);
        cudaStreamCreateWithFlags(&sLp, cudaStreamNonBlocking);
        cudaEventCreateWithFlags(&evRoot, cudaEventDisableTiming);
        cudaEventCreateWithFlags(&evPrep, cudaEventDisableTiming);
        cudaEventCreateWithFlags(&evZ, cudaEventDisableTiming);
        cudaEventCreateWithFlags(&evLp, cudaEventDisableTiming);
    }

    cudaEventRecord(evRoot, 0);
    cudaStreamWaitEvent(sPrep, evRoot, 0);

    // ---- side stream: edge prep ----
    detect_kernel<<<1, 32, 0, sPrep>>>((const long long*)ei);
    cudaMemsetAsync(degp, 0, (size_t)N * sizeof(int), sPrep);
    convert_hist_kernel<<<ebk, 256, 0, sPrep>>>(ei, E);
    scan_p1_kernel<<<nb, 256, 0, sPrep>>>(N);
    scan_p2_kernel<<<1, 256, 0, sPrep>>>(nb, N);
    scan_p3_kernel<<<nb, 256, 0, sPrep>>>(N);
    scatter_kernel<<<ebk, 256, 0, sPrep>>>(E);
    cudaEventRecord(evPrep, sPrep);

    // ---- main stream: splits + encoder GEMM1 ----
    wsplit_all_kernel<<<(77824 + 255) / 256, 256>>>(ew1, ew2, efw, dw1, dw2, wthi, wtlo);
    wsplit_dfw_f16_kernel<<<(1024 * 128 + 255) / 256, 256>>>(dfw, (__half*)(wthi + O_DFW));
    split_kernel<<<(N * 128 + 255) / 256, 256>>>(x, ahi, alo, N * 128);
    mma_gemm_kernel<0,0,0><<<dim3(2, rT), 256>>>(
        ahi, alo, wthi + O_EW1, wtlo + O_EW1, nullptr, bufA, nullptr, nullptr, N, 128, 128);

    cudaStreamWaitEvent(0, evPrep, 0);

    agg_split_kernel<128, 1, 1><<<aggB, 256>>>(bufA, eb1, ahi, alo, N);
    mma_gemm_kernel<0,0,0><<<dim3(1, rT), 256>>>(
        ahi, alo, wthi + O_EW2, wtlo + O_EW2, nullptr, bufA, nullptr, nullptr, N, 64, 128);
    agg_split_kernel<64, 0, 1><<<aggB, 256>>>(bufA, eb2, ahi, alo, N);
    mma_gemm_kernel<1,0,0><<<dim3(1, rT), 256>>>(
        ahi, alo, wthi + O_EFW, wtlo + O_EFW, efb, zbuf, nullptr, nullptr, N, 64, 64);

    cudaEventRecord(evZ, 0);
    cudaStreamWaitEvent(sLp, evZ, 0);
    lp_node_kernel<<<nb, 256, 0, sLp>>>(zbuf, lw, N);
    lp_edge_kernel<<<ebk, 256, 0, sLp>>>(lb, eprob, E);
    cudaEventRecord(evLp, sLp);

    // ---- decoder ----
    agg_split_kernel<64, 0, 0><<<aggB, 256>>>(zbuf, nullptr, ahi, alo, N);
    mma_gemm_kernel<1,1,1><<<dim3(4, rT), 256>>>(
        ahi, alo, wthi + O_DW1, wtlo + O_DW1, db1, nullptr, bhi, blo, N, 256, 64);
    mma_gemm_kernel<0,0,0><<<dim3(2, rT), 256>>>(
        bhi, blo, wthi + O_DW2, wtlo + O_DW2, nullptr, bufA, nullptr, nullptr, N, 128, 256);
    // agg4: fp16 hi/lo output (bias fused), feeds fp16 2-product final GEMM
    agg_split_f16_kernel<128><<<aggB, 256>>>(bufA, db2, (__half*)ahi, (__half*)alo, N);
    mma_gemm_f16_kernel<<<dim3(16, rT), 256>>>(
        (__half*)ahi, (__half*)alo, (__half*)(wthi + O_DFW), dfb, xhat, N, 1024, 128);

    cudaStreamWaitEvent(0, evLp, 0);
}

// round 15
// speedup vs baseline: 3.2116x; 1.0481x over previous
#include <cuda_runtime.h>
#include <cuda_bf16.h>
#include <cuda_fp16.h>
#include <math.h>
#include <stdint.h>

#define NN 50000
#define EE 800000

// ---------------- device scratch ----------------
__device__ float g_bufA[NN * 256];
__device__ float g_z[NN * 64];
__device__ __nv_bfloat16 g_ahi[NN * 256];
__device__ __nv_bfloat16 g_alo[NN * 256];
__device__ __nv_bfloat16 g_bhi[NN * 256];
__device__ __nv_bfloat16 g_blo[NN * 256];
__device__ __nv_bfloat16 g_wthi[208896];
__device__ __nv_bfloat16 g_wtlo[208896];
__device__ int   g_deg[NN];
__device__ float g_dinv[NN];
__device__ float g_dinv2[NN];
__device__ int   g_rowstart[NN + 1];
__device__ int   g_cursor[NN];
__device__ int   g_bsum[256];
__device__ int   g_boff[256];
__device__ int   g_src32[EE];
__device__ int   g_dst32[EE];
__device__ int   g_csr_src[EE];
__device__ float g_csr_norm[EE];
__device__ float g_t1[NN];
__device__ float g_t2[NN];
__device__ int   g_flag[1];

// ---------------- prep kernels ----------------
__global__ void detect_kernel(const long long* ei) {
    if (blockIdx.x == 0 && threadIdx.x == 0) {
        int ok = 1;
        for (int i = 0; i < 128; i++) {
            long long v = ei[i];
            if (v < 0 || v >= NN) { ok = 0; break; }
        }
        g_flag[0] = ok;
    }
}

__global__ void convert_hist_kernel(const void* ei, int E) {
    int i = blockIdx.x * blockDim.x + threadIdx.x;
    if (i >= E) return;
    int s, d;
    if (g_flag[0]) {
        const long long* p = (const long long*)ei;
        s = (int)p[i]; d = (int)p[i + E];
    } else {
        const int* p = (const int*)ei;
        s = p[i]; d = p[i + E];
    }
    g_src32[i] = s;
    g_dst32[i] = d;
    atomicAdd(&g_deg[d], 1);
}

__global__ __launch_bounds__(256) void scan_p1_kernel(int n) {
    __shared__ int wsum[8];
    int tid = threadIdx.x;
    int i = blockIdx.x * 256 + tid;
    int v = (i < n) ? g_deg[i] : 0;
    if (i < n) {
        float di = rsqrtf((float)(v + 1));
        g_dinv[i]  = di;
        g_dinv2[i] = di * di;
    }
    int x = v;
    #pragma unroll
    for (int o = 1; o < 32; o <<= 1) {
        int t = __shfl_up_sync(0xffffffffu, x, o);
        if ((tid & 31) >= o) x += t;
    }
    if ((tid & 31) == 31) wsum[tid >> 5] = x;
    __syncthreads();
    if (tid < 8) {
        int w = wsum[tid];
        #pragma unroll
        for (int o = 1; o < 8; o <<= 1) {
            int t = __shfl_up_sync(0xffu, w, o);
            if (tid >= o) w += t;
        }
        wsum[tid] = w;
    }
    __syncthreads();
    int incl = x + ((tid >= 32) ? wsum[(tid >> 5) - 1] : 0);
    if (i < n) g_rowstart[i] = incl - v;
    if (tid == 255) g_bsum[blockIdx.x] = incl;
}

__global__ __launch_bounds__(256) void scan_p2_kernel(int nb, int n) {
    __shared__ int wsum[8];
    int tid = threadIdx.x;
    int v = (tid < nb) ? g_bsum[tid] : 0;
    int x = v;
    #pragma unroll
    for (int o = 1; o < 32; o <<= 1) {
        int t = __shfl_up_sync(0xffffffffu, x, o);
        if ((tid & 31) >= o) x += t;
    }
    if ((tid & 31) == 31) wsum[tid >> 5] = x;
    __syncthreads();
    if (tid < 8) {
        int w = wsum[tid];
        #pragma unroll
        for (int o = 1; o < 8; o <<= 1) {
            int t = __shfl_up_sync(0xffu, w, o);
            if (tid >= o) w += t;
        }
        wsum[tid] = w;
    }
    __syncthreads();
    int incl = x + ((tid >= 32) ? wsum[(tid >> 5) - 1] : 0);
    if (tid < nb) g_boff[tid] = incl - v;
    if (tid == 255) g_rowstart[n] = incl;
}

__global__ __launch_bounds__(256) void scan_p3_kernel(int n) {
    int i = blockIdx.x * 256 + threadIdx.x;
    if (i >= n) return;
    int r = g_rowstart[i] + g_boff[blockIdx.x];
    g_rowstart[i] = r;
    g_cursor[i]   = r;
}

__global__ void scatter_kernel(int E) {
    int i = blockIdx.x * blockDim.x + threadIdx.x;
    if (i >= E) return;
    int s = g_src32[i], d = g_dst32[i];
    int pos = atomicAdd(&g_cursor[d], 1);
    g_csr_src[pos]  = s;
    g_csr_norm[pos] = g_dinv[s] * g_dinv[d];
}

// ---------------- split helpers ----------------
__device__ __forceinline__ void bf16_split(float v, __nv_bfloat16& h, __nv_bfloat16& l) {
    h = __float2bfloat16(v);
    l = __float2bfloat16(v - __bfloat162float(h));
}
__device__ __forceinline__ void f16_split(float v, __half& h, __half& l) {
    h = __float2half_rn(v);
    l = __float2half_rn(v - __half2float(h));
}
__device__ __forceinline__ void split2pack(float a, float b, uint32_t& h, uint32_t& l) {
    __nv_bfloat16 ha, la, hb, lb;
    bf16_split(a, ha, la);
    bf16_split(b, hb, lb);
    __nv_bfloat162 H(ha, hb), L(la, lb);
    h = *(uint32_t*)&H;
    l = *(uint32_t*)&L;
}

// weight transposes+splits for the 5 bf16 GEMMs
__global__ void wsplit_all_kernel(const float* __restrict__ ew1,
                                  const float* __restrict__ ew2,
                                  const float* __restrict__ efw,
                                  const float* __restrict__ dw1,
                                  const float* __restrict__ dw2,
                                  __nv_bfloat16* __restrict__ hi,
                                  __nv_bfloat16* __restrict__ lo) {
    int i = blockIdx.x * blockDim.x + threadIdx.x;
    if (i >= 77824) return;
    const float* W; int K, Nc, off;
    if (i < 16384)       { W = ew1; K = 128; Nc = 128;  off = 0; }
    else if (i < 24576)  { W = ew2; K = 128; Nc = 64;   off = 16384; }
    else if (i < 28672)  { W = efw; K = 64;  Nc = 64;   off = 24576; }
    else if (i < 45056)  { W = dw1; K = 64;  Nc = 256;  off = 28672; }
    else                 { W = dw2; K = 256; Nc = 128;  off = 45056; }
    int j = i - off;
    int n = j / K, k = j - n * K;
    __nv_bfloat16 h, l;
    bf16_split(W[(size_t)k * Nc + n], h, l);
    hi[i] = h; lo[i] = l;
}

__global__ void wsplit_dfw_f16_kernel(const float* __restrict__ W,
                                      __half* __restrict__ out) {
    int i = blockIdx.x * blockDim.x + threadIdx.x;   // [Nc=1024][K=128]
    if (i >= 1024 * 128) return;
    int n = i >> 7, k = i & 127;
    out[i] = __float2half_rn(W[(size_t)k * 1024 + n]);
}

// ---------------- mma.sync helpers ----------------
__device__ __forceinline__ void mma_bf16(float* c, const uint32_t* a, const uint32_t* b) {
    asm volatile(
        "mma.sync.aligned.m16n8k16.row.col.f32.bf16.bf16.f32 "
        "{%0,%1,%2,%3}, {%4,%5,%6,%7}, {%8,%9}, {%0,%1,%2,%3};"
        : "+f"(c[0]), "+f"(c[1]), "+f"(c[2]), "+f"(c[3])
        : "r"(a[0]), "r"(a[1]), "r"(a[2]), "r"(a[3]), "r"(b[0]), "r"(b[1]));
}
__device__ __forceinline__ void mma_f16(float* c, const uint32_t* a, const uint32_t* b) {
    asm volatile(
        "mma.sync.aligned.m16n8k16.row.col.f32.f16.f16.f32 "
        "{%0,%1,%2,%3}, {%4,%5,%6,%7}, {%8,%9}, {%0,%1,%2,%3};"
        : "+f"(c[0]), "+f"(c[1]), "+f"(c[2]), "+f"(c[3])
        : "r"(a[0]), "r"(a[1]), "r"(a[2]), "r"(a[3]), "r"(b[0]), "r"(b[1]));
}
__device__ __forceinline__ void ldsm_x4(uint32_t& r0, uint32_t& r1,
                                        uint32_t& r2, uint32_t& r3, uint32_t addr) {
    asm volatile("ldmatrix.sync.aligned.m8n8.x4.shared.b16 {%0,%1,%2,%3}, [%4];"
        : "=r"(r0), "=r"(r1), "=r"(r2), "=r"(r3) : "r"(addr));
}
__device__ __forceinline__ uint32_t smem_u32(const void* p) {
    uint32_t a;
    asm("{ .reg .u64 t; cvta.to.shared.u64 t, %1; cvt.u32.u64 %0, t; }"
        : "=r"(a) : "l"(p));
    return a;
}

#define PITCH 72

// ---------------- bf16 3-product GEMM ----------------
// AF32: A1 is fp32, converted to bf16 hi/lo during smem load (A2 unused).
// CF16: epilogue writes single fp16 to Cf16.
template<int BIAS, int RELU, int SPLIT, int AF32, int CF16>
__global__ __launch_bounds__(256) void mma_gemm_kernel(
    const void* A1, const void* A2,
    const __nv_bfloat16* __restrict__ Whi, const __nv_bfloat16* __restrict__ Wlo,
    const float* __restrict__ bias,
    float* __restrict__ Cf, __half* __restrict__ Cf16,
    __nv_bfloat16* __restrict__ Chi, __nv_bfloat16* __restrict__ Clo,
    int M, int Nc, int K, int rowOff)
{
    __shared__ __nv_bfloat16 sAhi[128 * PITCH];
    __shared__ __nv_bfloat16 sAlo[128 * PITCH];
    __shared__ __nv_bfloat16 sBhi[64 * PITCH];
    __shared__ __nv_bfloat16 sBlo[64 * PITCH];

    int tid  = threadIdx.x;
    int wid  = tid >> 5, lane = tid & 31;
    int wm   = wid & 3;
    int wn   = wid >> 2;
    int g    = lane >> 2;
    int t    = lane & 3;
    int bm   = rowOff + blockIdx.y * 128, bn = blockIdx.x * 64;

    float acc[2][4][4];
    #pragma unroll
    for (int i = 0; i < 2; i++)
        #pragma unroll
        for (int j = 0; j < 4; j++)
            #pragma unroll
            for (int r = 0; r < 4; r++) acc[i][j][r] = 0.f;

    int aRow0 = wm * 32 + (lane & 15);
    int aColB = (lane & 16) ? 16 : 0;
    uint32_t uAhi = smem_u32(sAhi), uAlo = smem_u32(sAlo);
    uint32_t aHi0 = uAhi + (uint32_t)(aRow0 * PITCH * 2 + aColB);
    uint32_t aLo0 = uAlo + (uint32_t)(aRow0 * PITCH * 2 + aColB);
    int bRow0 = wn * 32 + (lane & 7) + ((lane & 16) ? 8 : 0);
    int bColB = (lane & 8) ? 16 : 0;
    uint32_t uBhi = smem_u32(sBhi), uBlo = smem_u32(sBlo);
    uint32_t bHi0 = uBhi + (uint32_t)(bRow0 * PITCH * 2 + bColB);
    uint32_t bLo0 = uBlo + (uint32_t)(bRow0 * PITCH * 2 + bColB);
    const uint32_t AROWS16 = 16 * PITCH * 2;

    int arow = tid >> 1, ahalf = tid & 1;
    int btt = tid & 127;
    int brow = btt >> 1, bhalf = btt & 1;

    for (int kc = 0; kc < K; kc += 64) {
        __syncthreads();
        {
            __nv_bfloat16* dH = sAhi + arow * PITCH + ahalf * 32;
            __nv_bfloat16* dL = sAlo + arow * PITCH + ahalf * 32;
            int grow = bm + arow;
            if (grow < M) {
                if (AF32) {
                    const float4* xr = (const float4*)((const float*)A1 +
                        (size_t)grow * K + kc + ahalf * 32);
                    #pragma unroll
                    for (int c = 0; c < 4; c++) {
                        float4 f0 = xr[2 * c];
                        float4 f1 = xr[2 * c + 1];
                        uint32_t h0, l0, h1, l1, h2, l2, h3, l3;
                        split2pack(f0.x, f0.y, h0, l0);
                        split2pack(f0.z, f0.w, h1, l1);
                        split2pack(f1.x, f1.y, h2, l2);
                        split2pack(f1.z, f1.w, h3, l3);
                        ((uint4*)(dH + 8 * c))[0] = make_uint4(h0, h1, h2, h3);
                        ((uint4*)(dL + 8 * c))[0] = make_uint4(l0, l1, l2, l3);
                    }
                } else {
                    const uint4* sh = (const uint4*)((const __nv_bfloat16*)A1 +
                        (size_t)grow * K + kc + ahalf * 32);
                    const uint4* sl = (const uint4*)((const __nv_bfloat16*)A2 +
                        (size_t)grow * K + kc + ahalf * 32);
                    #pragma unroll
                    for (int c = 0; c < 4; c++) {
                        ((uint4*)dH)[c] = sh[c];
                        ((uint4*)dL)[c] = sl[c];
                    }
                }
            } else {
                uint4 z = make_uint4(0, 0, 0, 0);
                #pragma unroll
                for (int c = 0; c < 4; c++) { ((uint4*)dH)[c] = z; ((uint4*)dL)[c] = z; }
            }
        }
        {
            const __nv_bfloat16* W = (tid < 128) ? Whi : Wlo;
            __nv_bfloat16* dst = ((tid < 128) ? sBhi : sBlo) + brow * PITCH + bhalf * 32;
            const uint4* src = (const uint4*)(W + (size_t)(bn + brow) * K + kc + bhalf * 32);
            #pragma unroll
            for (int c = 0; c < 4; c++) ((uint4*)dst)[c] = src[c];
        }
        __syncthreads();

        #pragma unroll
        for (int ks = 0; ks < 4; ks++) {
            uint32_t ofs = ks * 32;
            uint32_t ah0[4], ah1[4], al0[4], al1[4];
            ldsm_x4(ah0[0], ah0[1], ah0[2], ah0[3], aHi0 + ofs);
            ldsm_x4(ah1[0], ah1[1], ah1[2], ah1[3], aHi0 + AROWS16 + ofs);
            ldsm_x4(al0[0], al0[1], al0[2], al0[3], aLo0 + ofs);
            ldsm_x4(al1[0], al1[1], al1[2], al1[3], aLo0 + AROWS16 + ofs);
            uint32_t bh[4][2], bl[4][2];
            ldsm_x4(bh[0][0], bh[0][1], bh[1][0], bh[1][1], bHi0 + ofs);
            ldsm_x4(bh[2][0], bh[2][1], bh[3][0], bh[3][1], bHi0 + AROWS16 + ofs);
            ldsm_x4(bl[0][0], bl[0][1], bl[1][0], bl[1][1], bLo0 + ofs);
            ldsm_x4(bl[2][0], bl[2][1], bl[3][0], bl[3][1], bLo0 + AROWS16 + ofs);
            #pragma unroll
            for (int na = 0; na < 4; na++) {
                mma_bf16(acc[0][na], ah0, bh[na]);
                mma_bf16(acc[0][na], ah0, bl[na]);
                mma_bf16(acc[0][na], al0, bh[na]);
                mma_bf16(acc[1][na], ah1, bh[na]);
                mma_bf16(acc[1][na], ah1, bl[na]);
                mma_bf16(acc[1][na], al1, bh[na]);
            }
        }
    }

    #pragma unroll
    for (int ma = 0; ma < 2; ma++) {
        #pragma unroll
        for (int half = 0; half < 2; half++) {
            int row = bm + wm * 32 + ma * 16 + g + half * 8;
            if (row >= M) continue;
            #pragma unroll
            for (int na = 0; na < 4; na++) {
                int col = bn + wn * 32 + na * 8 + 2 * t;
                float v0 = acc[ma][na][half * 2 + 0];
                float v1 = acc[ma][na][half * 2 + 1];
                if (BIAS) { v0 += __ldg(bias + col); v1 += __ldg(bias + col + 1); }
                if (RELU) { v0 = fmaxf(v0, 0.f); v1 = fmaxf(v1, 0.f); }
                if (SPLIT) {
                    __nv_bfloat16 h0, l0, h1, l1;
                    bf16_split(v0, h0, l0);
                    bf16_split(v1, h1, l1);
                    *(__nv_bfloat162*)(Chi + (size_t)row * Nc + col) = __nv_bfloat162(h0, h1);
                    *(__nv_bfloat162*)(Clo + (size_t)row * Nc + col) = __nv_bfloat162(l0, l1);
                } else if (CF16) {
                    *(__half2*)(Cf16 + (size_t)row * Nc + col) =
                        __half2(__float2half_rn(v0), __float2half_rn(v1));
                } else {
                    *(float2*)(Cf + (size_t)row * Nc + col) = make_float2(v0, v1);
                }
            }
        }
    }
}

// ---------------- fp16 2-product GEMM (final output layer) ----------------
__global__ __launch_bounds__(256) void mma_gemm_f16_kernel(
    const __half* __restrict__ Ahi, const __half* __restrict__ Alo,
    const __half* __restrict__ W,
    const float* __restrict__ bias,
    float* __restrict__ Cf,
    int M, int Nc, int K, int rowOff)
{
    __shared__ __half sAhi[128 * PITCH];
    __shared__ __half sAlo[128 * PITCH];
    __shared__ __half sB[64 * PITCH];

    int tid  = threadIdx.x;
    int wid  = tid >> 5, lane = tid & 31;
    int wm   = wid & 3;
    int wn   = wid >> 2;
    int g    = lane >> 2;
    int t    = lane & 3;
    int bm   = rowOff + blockIdx.y * 128, bn = blockIdx.x * 64;

    float acc[2][4][4];
    #pragma unroll
    for (int i = 0; i < 2; i++)
        #pragma unroll
        for (int j = 0; j < 4; j++)
            #pragma unroll
            for (int r = 0; r < 4; r++) acc[i][j][r] = 0.f;

    int aRow0 = wm * 32 + (lane & 15);
    int aColB = (lane & 16) ? 16 : 0;
    uint32_t uAhi = smem_u32(sAhi), uAlo = smem_u32(sAlo);
    uint32_t aHi0 = uAhi + (uint32_t)(aRow0 * PITCH * 2 + aColB);
    uint32_t aLo0 = uAlo + (uint32_t)(aRow0 * PITCH * 2 + aColB);
    int bRow0 = wn * 32 + (lane & 7) + ((lane & 16) ? 8 : 0);
    int bColB = (lane & 8) ? 16 : 0;
    uint32_t uB = smem_u32(sB);
    uint32_t bB0 = uB + (uint32_t)(bRow0 * PITCH * 2 + bColB);
    const uint32_t AROWS16 = 16 * PITCH * 2;

    int arow = tid >> 1, ahalf = tid & 1;
    int btt = tid & 127;
    int brow = btt >> 1, bhalf = btt & 1;

    for (int kc = 0; kc < K; kc += 64) {
        __syncthreads();
        {
            __half* dH = sAhi + arow * PITCH + ahalf * 32;
            __half* dL = sAlo + arow * PITCH + ahalf * 32;
            int grow = bm + arow;
            if (grow < M) {
                const uint4* sh = (const uint4*)(Ahi + (size_t)grow * K + kc + ahalf * 32);
                const uint4* sl = (const uint4*)(Alo + (size_t)grow * K + kc + ahalf * 32);
                #pragma unroll
                for (int c = 0; c < 4; c++) {
                    ((uint4*)dH)[c] = sh[c];
                    ((uint4*)dL)[c] = sl[c];
                }
            } else {
                uint4 z = make_uint4(0, 0, 0, 0);
                #pragma unroll
                for (int c = 0; c < 4; c++) { ((uint4*)dH)[c] = z; ((uint4*)dL)[c] = z; }
            }
        }
        if (tid < 128) {
            __half* dst = sB + brow * PITCH + bhalf * 32;
            const uint4* src = (const uint4*)(W + (size_t)(bn + brow) * K + kc + bhalf * 32);
            #pragma unroll
            for (int c = 0; c < 4; c++) ((uint4*)dst)[c] = src[c];
        }
        __syncthreads();

        #pragma unroll
        for (int ks = 0; ks < 4; ks++) {
            uint32_t ofs = ks * 32;
            uint32_t ah0[4], ah1[4], al0[4], al1[4];
            ldsm_x4(ah0[0], ah0[1], ah0[2], ah0[3], aHi0 + ofs);
            ldsm_x4(ah1[0], ah1[1], ah1[2], ah1[3], aHi0 + AROWS16 + ofs);
            ldsm_x4(al0[0], al0[1], al0[2], al0[3], aLo0 + ofs);
            ldsm_x4(al1[0], al1[1], al1[2], al1[3], aLo0 + AROWS16 + ofs);
            uint32_t b[4][2];
            ldsm_x4(b[0][0], b[0][1], b[1][0], b[1][1], bB0 + ofs);
            ldsm_x4(b[2][0], b[2][1], b[3][0], b[3][1], bB0 + AROWS16 + ofs);
            #pragma unroll
            for (int na = 0; na < 4; na++) {
                mma_f16(acc[0][na], ah0, b[na]);
                mma_f16(acc[0][na], al0, b[na]);
                mma_f16(acc[1][na], ah1, b[na]);
                mma_f16(acc[1][na], al1, b[na]);
            }
        }
    }

    #pragma unroll
    for (int ma = 0; ma < 2; ma++) {
        #pragma unroll
        for (int half = 0; half < 2; half++) {
            int row = bm + wm * 32 + ma * 16 + g + half * 8;
            if (row >= M) continue;
            #pragma unroll
            for (int na = 0; na < 4; na++) {
                int col = bn + wn * 32 + na * 8 + 2 * t;
                float v0 = acc[ma][na][half * 2 + 0] + __ldg(bias + col);
                float v1 = acc[ma][na][half * 2 + 1] + __ldg(bias + col + 1);
                asm volatile("st.global.cs.v2.f32 [%0], {%1, %2};"
                    :: "l"(Cf + (size_t)row * Nc + col), "f"(v0), "f"(v1));
            }
        }
    }
}

// ---------------- fp32-gather aggregation, bf16 hi/lo output ----------------
template<int F, int RELU, int BIAS>
__global__ __launch_bounds__(256) void agg_split_kernel(
    const float* __restrict__ h, const float* __restrict__ bias,
    __nv_bfloat16* __restrict__ outHi, __nv_bfloat16* __restrict__ outLo,
    int n0, int n1)
{
    int gw = n0 + ((blockIdx.x * blockDim.x + threadIdx.x) >> 5);
    int lane = threadIdx.x & 31;
    if (gw >= n1) return;
    constexpr int V = F / 32;
    float acc[V];
    #pragma unroll
    for (int i = 0; i < V; i++) acc[i] = 0.f;
    int e0 = g_rowstart[gw], e1 = g_rowstart[gw + 1];
    const float* basep = h + lane * V;
    #pragma unroll 2
    for (int e = e0; e < e1; e++) {
        int s = __ldg(&g_csr_src[e]);
        float w = __ldg(&g_csr_norm[e]);
        const float* r = basep + (size_t)s * F;
        if (V == 2) {
            float2 x2 = *(const float2*)r;
            acc[0] += x2.x * w; acc[1] += x2.y * w;
        } else {
            #pragma unroll
            for (int i = 0; i < V; i += 4) {
                float4 x4 = *(const float4*)(r + i);
                acc[i + 0] += x4.x * w; acc[i + 1] += x4.y * w;
                acc[i + 2] += x4.z * w; acc[i + 3] += x4.w * w;
            }
        }
    }
    float sw = g_dinv2[gw];
    const float* sr = basep + (size_t)gw * F;
    __nv_bfloat16* oh = outHi + (size_t)gw * F + lane * V;
    __nv_bfloat16* ol = outLo + (size_t)gw * F + lane * V;
    #pragma unroll
    for (int i = 0; i < V; i += 2) {
        float v0 = acc[i] + sr[i] * sw;
        float v1 = acc[i + 1] + sr[i + 1] * sw;
        if (BIAS) { v0 += bias[lane * V + i]; v1 += bias[lane * V + i + 1]; }
        if (RELU) { v0 = fmaxf(v0, 0.f); v1 = fmaxf(v1, 0.f); }
        __nv_bfloat16 h0, l0, h1, l1;
        bf16_split(v0, h0, l0);
        bf16_split(v1, h1, l1);
        *(__nv_bfloat162*)(oh + i) = __nv_bfloat162(h0, h1);
        *(__nv_bfloat162*)(ol + i) = __nv_bfloat162(l0, l1);
    }
}

// ---------------- fp16-gather aggregation (F=128) ----------------
// OUTF16=0: bf16 hi/lo out; OUTF16=1: fp16 hi/lo out.
template<int RELU, int BIAS, int OUTF16>
__global__ __launch_bounds__(256) void agg_f16g_kernel(
    const __half* __restrict__ h, const float* __restrict__ bias,
    void* outHi_, void* outLo_, int n0, int n1)
{
    int gw = n0 + ((blockIdx.x * blockDim.x + threadIdx.x) >> 5);
    int lane = threadIdx.x & 31;
    if (gw >= n1) return;
    float acc[4] = {0.f, 0.f, 0.f, 0.f};
    int e0 = g_rowstart[gw], e1 = g_rowstart[gw + 1];
    const __half* basep = h + lane * 4;
    #pragma unroll 2
    for (int e = e0; e < e1; e++) {
        int s = __ldg(&g_csr_src[e]);
        float w = __ldg(&g_csr_norm[e]);
        uint2 u = *(const uint2*)(basep + (size_t)s * 128);
        float2 f0 = __half22float2(*(__half2*)&u.x);
        float2 f1 = __half22float2(*(__half2*)&u.y);
        acc[0] += f0.x * w; acc[1] += f0.y * w;
        acc[2] += f1.x * w; acc[3] += f1.y * w;
    }
    float sw = g_dinv2[gw];
    uint2 su = *(const uint2*)(basep + (size_t)gw * 128);
    float2 s0 = __half22float2(*(__half2*)&su.x);
    float2 s1 = __half22float2(*(__half2*)&su.y);
    float v[4];
    v[0] = acc[0] + s0.x * sw; v[1] = acc[1] + s0.y * sw;
    v[2] = acc[2] + s1.x * sw; v[3] = acc[3] + s1.y * sw;
    #pragma unroll
    for (int i = 0; i < 4; i++) {
        if (BIAS) v[i] += bias[lane * 4 + i];
        if (RELU) v[i] = fmaxf(v[i], 0.f);
    }
    if (OUTF16) {
        __half* oh = (__half*)outHi_ + (size_t)gw * 128 + lane * 4;
        __half* ol = (__half*)outLo_ + (size_t)gw * 128 + lane * 4;
        #pragma unroll
        for (int i = 0; i < 4; i += 2) {
            __half h0, l0, h1, l1;
            f16_split(v[i], h0, l0);
            f16_split(v[i + 1], h1, l1);
            *(__half2*)(oh + i) = __half2(h0, h1);
            *(__half2*)(ol + i) = __half2(l0, l1);
        }
    } else {
        __nv_bfloat16* oh = (__nv_bfloat16*)outHi_ + (size_t)gw * 128 + lane * 4;
        __nv_bfloat16* ol = (__nv_bfloat16*)outLo_ + (size_t)gw * 128 + lane * 4;
        #pragma unroll
        for (int i = 0; i < 4; i += 2) {
            __nv_bfloat16 h0, l0, h1, l1;
            bf16_split(v[i], h0, l0);
            bf16_split(v[i + 1], h1, l1);
            *(__nv_bfloat162*)(oh + i) = __nv_bfloat162(h0, h1);
            *(__nv_bfloat162*)(ol + i) = __nv_bfloat162(l0, l1);
        }
    }
}

// ---------------- link predictor ----------------
__global__ void lp_node_kernel(const float* __restrict__ z,
                               const float* __restrict__ lw, int N)
{
    int v = blockIdx.x * blockDim.x + threadIdx.x;
    if (v >= N) return;
    const float4* zr = (const float4*)(z + (size_t)v * 64);
    float a = 0.f, b = 0.f;
    #pragma unroll
    for (int i = 0; i < 16; i++) {
        float4 zz = zr[i];
        float4 w1 = __ldg(&((const float4*)lw)[i]);
        float4 w2 = __ldg(&((const float4*)lw)[16 + i]);
        a += zz.x * w1.x + zz.y * w1.y + zz.z * w1.z + zz.w * w1.w;
        b += zz.x * w2.x + zz.y * w2.y + zz.z * w2.z + zz.w * w2.w;
    }
    g_t1[v] = a;
    g_t2[v] = b;
}

__global__ void lp_edge_kernel(const float* __restrict__ lb,
                               float* __restrict__ out, int E)
{
    int e = blockIdx.x * blockDim.x + threadIdx.x;
    if (e >= E) return;
    float p = g_t1[g_src32[e]] + g_t2[g_dst32[e]] + lb[0];
    float v = 1.f / (1.f + expf(-p));
    asm volatile("st.global.cs.f32 [%0], %1;" :: "l"(out + e), "f"(v));
}

// ---------------- host launcher ----------------
extern "C" void kernel_launch(void* const* d_in, const int* in_sizes, int n_in,
                              void* d_out, int out_size)
{
    const float* x   = (const float*)d_in[0];
    const void*  ei  = d_in[1];
    const float* ew1 = (const float*)d_in[2];
    const float* eb1 = (const float*)d_in[3];
    const float* ew2 = (const float*)d_in[4];
    const float* eb2 = (const float*)d_in[5];
    const float* efw = (const float*)d_in[6];
    const float* efb = (const float*)d_in[7];
    const float* dw1 = (const float*)d_in[8];
    const float* db1 = (const float*)d_in[9];
    const float* dw2 = (const float*)d_in[10];
    const float* db2 = (const float*)d_in[11];
    const float* dfw = (const float*)d_in[12];
    const float* dfb = (const float*)d_in[13];
    const float* lw  = (const float*)d_in[14];
    const float* lb  = (const float*)d_in[15];

    int N = in_sizes[0] / 128;
    int E = in_sizes[1] / 2;
    if (N > NN) N = NN;
    if (E > EE) E = EE;

    float *bufA, *zbuf;
    __nv_bfloat16 *ahi, *alo, *bhi, *blo, *wthi, *wtlo;
    int* degp;
    cudaGetSymbolAddress((void**)&bufA, g_bufA);
    cudaGetSymbolAddress((void**)&zbuf, g_z);
    cudaGetSymbolAddress((void**)&ahi, g_ahi);
    cudaGetSymbolAddress((void**)&alo, g_alo);
    cudaGetSymbolAddress((void**)&bhi, g_bhi);
    cudaGetSymbolAddress((void**)&blo, g_blo);
    cudaGetSymbolAddress((void**)&wthi, g_wthi);
    cudaGetSymbolAddress((void**)&wtlo, g_wtlo);
    cudaGetSymbolAddress((void**)&degp, g_deg);

    const int O_EW1 = 0;
    const int O_EW2 = O_EW1 + 128 * 128;
    const int O_EFW = O_EW2 + 64 * 128;
    const int O_DW1 = O_EFW + 64 * 64;
    const int O_DW2 = O_DW1 + 256 * 64;
    const int O_DFW = O_DW2 + 128 * 256;   // fp16 region (reinterpreted)

    float* xhat  = (float*)d_out;
    float* eprob = (float*)d_out + (size_t)N * 1024;

    int nb  = (N + 255) / 256;
    int ebk = (E + 255) / 256;
    int rT  = (N + 127) / 128;

    // chunking (2 chunks of row tiles)
    int t0 = (rT + 1) / 2;           // 196
    int t1 = rT - t0;                // 195
    int NC0 = t0 * 128;              // 25088
    int aggB0 = (NC0 + 7) / 8;
    int aggB1 = (N - NC0 + 7) / 8;
    int aggB  = (N + 7) / 8;

    static cudaStream_t sPrep = nullptr, sLp = nullptr, sAux = nullptr;
    static cudaEvent_t evRoot, evPrep, evZ, evLp, evG1, evA1, evD2, evA4;
    if (!sPrep) {
        cudaStreamCreateWithFlags(&sPrep, cudaStreamNonBlocking);
        cudaStreamCreateWithFlags(&sLp, cudaStreamNonBlocking);
        cudaStreamCreateWithFlags(&sAux, cudaStreamNonBlocking);
        cudaEventCreateWithFlags(&evRoot, cudaEventDisableTiming);
        cudaEventCreateWithFlags(&evPrep, cudaEventDisableTiming);
        cudaEventCreateWithFlags(&evZ, cudaEventDisableTiming);
        cudaEventCreateWithFlags(&evLp, cudaEventDisableTiming);
        cudaEventCreateWithFlags(&evG1, cudaEventDisableTiming);
        cudaEventCreateWithFlags(&evA1, cudaEventDisableTiming);
        cudaEventCreateWithFlags(&evD2, cudaEventDisableTiming);
        cudaEventCreateWithFlags(&evA4, cudaEventDisableTiming);
    }

    cudaEventRecord(evRoot, 0);
    cudaStreamWaitEvent(sPrep, evRoot, 0);

    // ---- side stream: edge prep ----
    detect_kernel<<<1, 32, 0, sPrep>>>((const long long*)ei);
    cudaMemsetAsync(degp, 0, (size_t)N * sizeof(int), sPrep);
    convert_hist_kernel<<<ebk, 256, 0, sPrep>>>(ei, E);
    scan_p1_kernel<<<nb, 256, 0, sPrep>>>(N);
    scan_p2_kernel<<<1, 256, 0, sPrep>>>(nb, N);
    scan_p3_kernel<<<nb, 256, 0, sPrep>>>(N);
    scatter_kernel<<<ebk, 256, 0, sPrep>>>(E);
    cudaEventRecord(evPrep, sPrep);

    __half* h1buf = (__half*)zbuf;           // gemm1 fp16 output (NN*128 halfs)
    __half* h4buf = (__half*)bufA;           // dw2 gemm fp16 output

    // ---- main stream: weight prep + GEMM1 (x converted in-kernel) ----
    wsplit_all_kernel<<<(77824 + 255) / 256, 256>>>(ew1, ew2, efw, dw1, dw2, wthi, wtlo);
    wsplit_dfw_f16_kernel<<<(1024 * 128 + 255) / 256, 256>>>(dfw, (__half*)(wthi + O_DFW));
    mma_gemm_kernel<0,0,0,1,1><<<dim3(2, rT), 256>>>(
        x, nullptr, wthi + O_EW1, wtlo + O_EW1, nullptr,
        nullptr, h1buf, nullptr, nullptr, N, 128, 128, 0);

    cudaStreamWaitEvent(0, evPrep, 0);
    cudaEventRecord(evG1, 0);

    // agg1 chunked (fp16 gather, bf16 split out) overlapped with gemm_ew2(c0)
    agg_f16g_kernel<1,1,0><<<aggB0, 256>>>(h1buf, eb1, ahi, alo, 0, NC0);
    cudaStreamWaitEvent(sAux, evG1, 0);
    agg_f16g_kernel<1,1,0><<<aggB1, 256, 0, sAux>>>(h1buf, eb1, ahi, alo, NC0, N);
    cudaEventRecord(evA1, sAux);

    mma_gemm_kernel<0,0,0,0,0><<<dim3(1, t0), 256>>>(
        ahi, alo, wthi + O_EW2, wtlo + O_EW2, nullptr,
        bufA, nullptr, nullptr, nullptr, N, 64, 128, 0);
    cudaStreamWaitEvent(0, evA1, 0);
    mma_gemm_kernel<0,0,0,0,0><<<dim3(1, t1), 256>>>(
        ahi, alo, wthi + O_EW2, wtlo + O_EW2, nullptr,
        bufA, nullptr, nullptr, nullptr, N, 64, 128, NC0);

    agg_split_kernel<64, 0, 1><<<aggB, 256>>>(bufA, eb2, ahi, alo, 0, N);
    mma_gemm_kernel<1,0,0,0,0><<<dim3(1, rT), 256>>>(
        ahi, alo, wthi + O_EFW, wtlo + O_EFW, efb,
        zbuf, nullptr, nullptr, nullptr, N, 64, 64, 0);

    cudaEventRecord(evZ, 0);
    cudaStreamWaitEvent(sLp, evZ, 0);
    lp_node_kernel<<<nb, 256, 0, sLp>>>(zbuf, lw, N);
    lp_edge_kernel<<<ebk, 256, 0, sLp>>>(lb, eprob, E);
    cudaEventRecord(evLp, sLp);

    // ---- decoder ----
    agg_split_kernel<64, 0, 0><<<aggB, 256>>>(zbuf, nullptr, ahi, alo, 0, N);
    mma_gemm_kernel<1,1,1,0,0><<<dim3(4, rT), 256>>>(
        ahi, alo, wthi + O_DW1, wtlo + O_DW1, db1,
        nullptr, nullptr, bhi, blo, N, 256, 64, 0);
    mma_gemm_kernel<0,0,0,0,1><<<dim3(2, rT), 256>>>(
        bhi, blo, wthi + O_DW2, wtlo + O_DW2, nullptr,
        nullptr, h4buf, nullptr, nullptr, N, 128, 256, 0);
    cudaEventRecord(evD2, 0);

    // agg4 chunked (fp16 gather, fp16 split out) overlapped with final GEMM(c0)
    agg_f16g_kernel<0,1,1><<<aggB0, 256>>>(h4buf, db2, (__half*)ahi, (__half*)alo, 0, NC0);
    cudaStreamWaitEvent(sAux, evD2, 0);
    agg_f16g_kernel<0,1,1><<<aggB1, 256, 0, sAux>>>(h4buf, db2, (__half*)ahi, (__half*)alo, NC0, N);
    cudaEventRecord(evA4, sAux);

    mma_gemm_f16_kernel<<<dim3(16, t0), 256>>>(
        (__half*)ahi, (__half*)alo, (__half*)(wthi + O_DFW), dfb, xhat, N, 1024, 128, 0);
    cudaStreamWaitEvent(0, evA4, 0);
    mma_gemm_f16_kernel<<<dim3(16, t1), 256>>>(
        (__half*)ahi, (__half*)alo, (__half*)(wthi + O_DFW), dfb, xhat, N, 1024, 128, NC0);

    cudaStreamWaitEvent(0, evLp, 0);
}